// round 11
// baseline (speedup 1.0000x reference)
#include <cuda_runtime.h>
#include <math.h>
#include <stdint.h>

#define NN 50000
#define NE 800000
#define D  128
#define DO 64
#define NC 40
#define SCAN_T 512
#define SCAN_B ((NN + SCAN_T - 1) / SCAN_T)   // 98

#define ASTR2 20   // uint2 stride per node (paired A layout)
#define WSTR2 132  // uint2 stride per pair-row (paired W layout)

// Scratch (device globals: no allocation allowed)
__device__ float g_agg[(size_t)NN * D];
__device__ float g_x1[(size_t)NN * D];
__device__ float g_x2[(size_t)NN * D];
__device__ float g_p[(size_t)NN * DO];
__device__ float g_q[(size_t)NN * DO];
__device__ int   g_deg[NN];
__device__ int   g_off[NN];
__device__ int   g_cur[NN];
__device__ int   g_bsum[SCAN_B];
__device__ int   g_esrc[NE];

__device__ __forceinline__ float gelu_exact(float v) {
    return 0.5f * v * (1.0f + erff(v * 0.70710678118654752f));
}

__device__ __forceinline__ uint32_t f2tf32(float f) {
    uint32_t r;
    asm("cvt.rna.tf32.f32 %0, %1;" : "=r"(r) : "f"(f));
    return r;
}

__device__ __forceinline__ void mma_tf32(float* d,
    uint32_t a0, uint32_t a1, uint32_t a2, uint32_t a3,
    uint32_t b0, uint32_t b1)
{
    asm volatile(
        "mma.sync.aligned.m16n8k8.row.col.f32.tf32.tf32.f32 "
        "{%0,%1,%2,%3}, {%4,%5,%6,%7}, {%8,%9}, {%0,%1,%2,%3};"
        : "+f"(d[0]), "+f"(d[1]), "+f"(d[2]), "+f"(d[3])
        : "r"(a0), "r"(a1), "r"(a2), "r"(a3), "r"(b0), "r"(b1));
}

// ---------------- CSR build ----------------

__global__ void zero_deg_cur() {
    int i = blockIdx.x * blockDim.x + threadIdx.x;
    if (i < NN) { g_deg[i] = 0; g_cur[i] = 0; }
}

__global__ void count_deg(const int* __restrict__ dst) {
    int e = blockIdx.x * blockDim.x + threadIdx.x;
    if (e < NE) atomicAdd(&g_deg[dst[e]], 1);
}

__global__ void scan_local() {
    __shared__ int s[SCAN_T];
    int t = threadIdx.x;
    int i = blockIdx.x * SCAN_T + t;
    int v = (i < NN) ? g_deg[i] : 0;
    s[t] = v;
    __syncthreads();
    #pragma unroll
    for (int off = 1; off < SCAN_T; off <<= 1) {
        int a = (t >= off) ? s[t - off] : 0;
        __syncthreads();
        s[t] += a;
        __syncthreads();
    }
    if (i < NN) g_off[i] = s[t] - v;
    if (t == SCAN_T - 1) g_bsum[blockIdx.x] = s[t];
}

// Each block redundantly scans the 98 block sums, then applies to its slice.
__global__ void scan_add2() {   // <<<(NN+255)/256, 128>>>, 2 elems/thread
    __shared__ int s[128];
    int t = threadIdx.x;
    int v = (t < SCAN_B) ? g_bsum[t] : 0;
    s[t] = v;
    __syncthreads();
    #pragma unroll
    for (int off = 1; off < 128; off <<= 1) {
        int a = (t >= off) ? s[t - off] : 0;
        __syncthreads();
        s[t] += a;
        __syncthreads();
    }
    int inc = s[t];
    __syncthreads();
    s[t] = inc - v;                               // exclusive
    __syncthreads();
    int i0 = blockIdx.x * 256 + t;
    int i1 = i0 + 128;
    if (i0 < NN) g_off[i0] += s[i0 / SCAN_T];
    if (i1 < NN) g_off[i1] += s[i1 / SCAN_T];
}

__global__ void fill_edges(const int* __restrict__ src, const int* __restrict__ dst) {
    int e = blockIdx.x * blockDim.x + threadIdx.x;
    if (e >= NE) return;
    int d = dst[e];
    int pos = g_off[d] + atomicAdd(&g_cur[d], 1);
    g_esrc[pos] = src[e];
}

// ---------------- gather mean-aggregation (warp/node, 4-way unrolled) --------

__global__ __launch_bounds__(256) void gather128(const float* __restrict__ x) {
    int gw = (blockIdx.x * blockDim.x + threadIdx.x) >> 5;
    int lane = threadIdx.x & 31;
    if (gw >= NN) return;
    int start = g_off[gw], deg = g_deg[gw];
    const int* es = g_esrc + start;
    const float4* x4 = (const float4*)x;
    float4 a0 = make_float4(0.f,0.f,0.f,0.f), a1 = a0, a2 = a0, a3 = a0;
    int e = 0;
    for (; e + 4 <= deg; e += 4) {
        int s0 = __ldg(es + e),     s1 = __ldg(es + e + 1);
        int s2 = __ldg(es + e + 2), s3 = __ldg(es + e + 3);
        float4 v0 = __ldg(&x4[(size_t)s0 * 32 + lane]);
        float4 v1 = __ldg(&x4[(size_t)s1 * 32 + lane]);
        float4 v2 = __ldg(&x4[(size_t)s2 * 32 + lane]);
        float4 v3 = __ldg(&x4[(size_t)s3 * 32 + lane]);
        a0.x += v0.x; a0.y += v0.y; a0.z += v0.z; a0.w += v0.w;
        a1.x += v1.x; a1.y += v1.y; a1.z += v1.z; a1.w += v1.w;
        a2.x += v2.x; a2.y += v2.y; a2.z += v2.z; a2.w += v2.w;
        a3.x += v3.x; a3.y += v3.y; a3.z += v3.z; a3.w += v3.w;
    }
    for (; e < deg; e++) {
        int s0 = __ldg(es + e);
        float4 v0 = __ldg(&x4[(size_t)s0 * 32 + lane]);
        a0.x += v0.x; a0.y += v0.y; a0.z += v0.z; a0.w += v0.w;
    }
    float inv = 1.0f / fmaxf((float)deg, 1.0f);
    float4 r;
    r.x = (a0.x + a1.x + a2.x + a3.x) * inv;
    r.y = (a0.y + a1.y + a2.y + a3.y) * inv;
    r.z = (a0.z + a1.z + a2.z + a3.z) * inv;
    r.w = (a0.w + a1.w + a2.w + a3.w) * inv;
    ((float4*)g_agg)[(size_t)gw * 32 + lane] = r;
}

// ---- fused SAGE block: tf32 mma, 32x32 warp tiles, paired uint2 operands ----
// h = [agg; x] @ [Wl; Wr] + bl -> LN -> GELU -> + x.
// Block: 64 nodes x 128 cols; 8 warps: wm=warp&1 (32 nodes), wn=warp>>1 (32 cols).
// K streamed in chunks of 32. Paired smem layouts: one 64-bit LDS per fragment.

__global__ __launch_bounds__(256, 2) void sage_tc2(
    const float* __restrict__ xin,
    const float* __restrict__ Wl, const float* __restrict__ bl,
    const float* __restrict__ Wr,
    const float* __restrict__ gma, const float* __restrict__ bta,
    float* __restrict__ xout)
{
    __shared__ uint2 Apk[64 * ASTR2];     // 10240 B
    __shared__ uint2 Wpk[16 * WSTR2];     // 16896 B
    __shared__ float sred[4][64][2];      //  2048 B

    const int tid = threadIdx.x;
    const int node0 = blockIdx.x * 64;
    const int warp = tid >> 5, lane = tid & 31;
    const int wm = warp & 1, wn = warp >> 1;
    const int g = lane >> 2, t4 = lane & 3;

    const int an0 = tid >> 3, an1 = (tid + 256) >> 3, af = tid & 7;
    const int koff = (af >> 1) * 8 + (af & 1);
    const float4 f4z = make_float4(0.f, 0.f, 0.f, 0.f);

    auto ldA = [&](int kc, float4& r0, float4& r1) {
        const float4* Asrc = (kc < 4) ? (const float4*)g_agg : (const float4*)xin;
        int kb = (kc & 3) * 8;
        int gn0 = node0 + an0, gn1 = node0 + an1;
        r0 = (gn0 < NN) ? __ldg(&Asrc[(size_t)gn0 * 32 + kb + af]) : f4z;
        r1 = (gn1 < NN) ? __ldg(&Asrc[(size_t)gn1 * 32 + kb + af]) : f4z;
    };
    auto stA = [&](float4 r0, float4 r1) {
        uint32_t* Au = (uint32_t*)Apk;
        Au[an0 * 40 + koff + 0] = f2tf32(r0.x);
        Au[an0 * 40 + koff + 2] = f2tf32(r0.y);
        Au[an0 * 40 + koff + 4] = f2tf32(r0.z);
        Au[an0 * 40 + koff + 6] = f2tf32(r0.w);
        Au[an1 * 40 + koff + 0] = f2tf32(r1.x);
        Au[an1 * 40 + koff + 2] = f2tf32(r1.y);
        Au[an1 * 40 + koff + 4] = f2tf32(r1.z);
        Au[an1 * 40 + koff + 6] = f2tf32(r1.w);
    };
    auto ldW = [&](int kc, float4* w) {
        const float4* Wsrc = (kc < 4) ? (const float4*)Wl : (const float4*)Wr;
        int kr0 = (kc & 3) * 32;
        int p0 = 2 * warp, p1 = 2 * warp + 1;
        int k0 = (p0 >> 2) * 8 + (p0 & 3);
        int k1 = (p1 >> 2) * 8 + (p1 & 3);
        w[0] = __ldg(&Wsrc[(size_t)(kr0 + k0) * 32 + lane]);
        w[1] = __ldg(&Wsrc[(size_t)(kr0 + k0 + 4) * 32 + lane]);
        w[2] = __ldg(&Wsrc[(size_t)(kr0 + k1) * 32 + lane]);
        w[3] = __ldg(&Wsrc[(size_t)(kr0 + k1 + 4) * 32 + lane]);
    };
    auto stW = [&](const float4* w) {
        uint4* W4 = (uint4*)Wpk;
        #pragma unroll
        for (int q = 0; q < 2; q++) {
            int p = 2 * warp + q;
            float4 lo = w[2 * q], hi = w[2 * q + 1];
            W4[p * 66 + 2 * lane]     = make_uint4(f2tf32(lo.x), f2tf32(hi.x),
                                                   f2tf32(lo.y), f2tf32(hi.y));
            W4[p * 66 + 2 * lane + 1] = make_uint4(f2tf32(lo.z), f2tf32(hi.z),
                                                   f2tf32(lo.w), f2tf32(hi.w));
        }
    };

    float acc0[4][4], acc1[4][4];
    #pragma unroll
    for (int i = 0; i < 4; i++)
        #pragma unroll
        for (int j = 0; j < 4; j++) { acc0[i][j] = 0.f; acc1[i][j] = 0.f; }

    {
        float4 a0, a1, w0[4];
        ldA(0, a0, a1); ldW(0, w0);
        stA(a0, a1); stW(w0);
    }
    __syncthreads();

    const int C = wm * 32;
    for (int kc = 0; kc < 8; kc++) {
        float4 na0, na1, nw[4];
        if (kc < 7) { ldA(kc + 1, na0, na1); ldW(kc + 1, nw); }
        #pragma unroll
        for (int kk = 0; kk < 4; kk++) {
            int pbase = kk * 4 + t4;
            uint2 qa0 = Apk[(C + g)      * ASTR2 + pbase];
            uint2 qa1 = Apk[(C + g + 8)  * ASTR2 + pbase];
            uint2 qa2 = Apk[(C + g + 16) * ASTR2 + pbase];
            uint2 qa3 = Apk[(C + g + 24) * ASTR2 + pbase];
            #pragma unroll
            for (int nt = 0; nt < 4; nt++) {
                uint2 qb = Wpk[pbase * WSTR2 + wn * 32 + nt * 8 + g];
                mma_tf32(acc0[nt], qa0.x, qa1.x, qa0.y, qa1.y, qb.x, qb.y);
                mma_tf32(acc1[nt], qa2.x, qa3.x, qa2.y, qa3.y, qb.x, qb.y);
            }
        }
        __syncthreads();
        if (kc < 7) { stA(na0, na1); stW(nw); __syncthreads(); }
    }

    // ---- epilogue: + bl -> LN (128 cols) -> GELU -> + residual ----
    float s[4][2];
    #pragma unroll
    for (int r = 0; r < 4; r++) { s[r][0] = 0.f; s[r][1] = 0.f; }
    #pragma unroll
    for (int nt = 0; nt < 4; nt++) {
        int c = wn * 32 + nt * 8 + 2 * t4;
        float2 blv = *(const float2*)&bl[c];
        acc0[nt][0] += blv.x; acc0[nt][1] += blv.y;
        acc0[nt][2] += blv.x; acc0[nt][3] += blv.y;
        acc1[nt][0] += blv.x; acc1[nt][1] += blv.y;
        acc1[nt][2] += blv.x; acc1[nt][3] += blv.y;
        s[0][0] += acc0[nt][0] + acc0[nt][1];
        s[0][1] += acc0[nt][0]*acc0[nt][0] + acc0[nt][1]*acc0[nt][1];
        s[1][0] += acc0[nt][2] + acc0[nt][3];
        s[1][1] += acc0[nt][2]*acc0[nt][2] + acc0[nt][3]*acc0[nt][3];
        s[2][0] += acc1[nt][0] + acc1[nt][1];
        s[2][1] += acc1[nt][0]*acc1[nt][0] + acc1[nt][1]*acc1[nt][1];
        s[3][0] += acc1[nt][2] + acc1[nt][3];
        s[3][1] += acc1[nt][2]*acc1[nt][2] + acc1[nt][3]*acc1[nt][3];
    }
    #pragma unroll
    for (int off = 1; off <= 2; off <<= 1)
        #pragma unroll
        for (int r = 0; r < 4; r++) {
            s[r][0] += __shfl_xor_sync(0xffffffffu, s[r][0], off);
            s[r][1] += __shfl_xor_sync(0xffffffffu, s[r][1], off);
        }
    if (t4 == 0) {
        #pragma unroll
        for (int r = 0; r < 4; r++) {
            sred[wn][C + g + r * 8][0] = s[r][0];
            sred[wn][C + g + r * 8][1] = s[r][1];
        }
    }
    __syncthreads();

    float mu[4], rs[4];
    #pragma unroll
    for (int r = 0; r < 4; r++) {
        int row = C + g + r * 8;
        float S1 = sred[0][row][0] + sred[1][row][0] + sred[2][row][0] + sred[3][row][0];
        float S2 = sred[0][row][1] + sred[1][row][1] + sred[2][row][1] + sred[3][row][1];
        mu[r] = S1 * (1.0f / 128.0f);
        float var = S2 * (1.0f / 128.0f) - mu[r] * mu[r];
        rs[r] = rsqrtf(var + 1e-5f);
    }

    #pragma unroll
    for (int nt = 0; nt < 4; nt++) {
        int c = wn * 32 + nt * 8 + 2 * t4;
        float2 gv = *(const float2*)&gma[c];
        float2 bv = *(const float2*)&bta[c];
        #pragma unroll
        for (int r = 0; r < 4; r++) {
            int gn = node0 + C + g + r * 8;
            if (gn >= NN) continue;
            float v0, v1;
            if (r == 0)      { v0 = acc0[nt][0]; v1 = acc0[nt][1]; }
            else if (r == 1) { v0 = acc0[nt][2]; v1 = acc0[nt][3]; }
            else if (r == 2) { v0 = acc1[nt][0]; v1 = acc1[nt][1]; }
            else             { v0 = acc1[nt][2]; v1 = acc1[nt][3]; }
            float2 res = *(const float2*)&xin[(size_t)gn * D + c];
            float o0 = gelu_exact((v0 - mu[r]) * rs[r] * gv.x + bv.x) + res.x;
            float o1 = gelu_exact((v1 - mu[r]) * rs[r] * gv.y + bv.y) + res.y;
            *(float2*)&xout[(size_t)gn * D + c] = make_float2(o0, o1);
        }
    }
}

// ---- gemm_pq: [p | q] = x2 @ [Wl3 | Wr3]  (tf32, K=128) ----

__global__ __launch_bounds__(256, 2) void gemm_pq(
    const float* __restrict__ Wl3, const float* __restrict__ Wr3)
{
    __shared__ uint2 Apk[64 * ASTR2];
    __shared__ uint2 Wpk[16 * WSTR2];

    const int tid = threadIdx.x;
    const int node0 = blockIdx.x * 64;
    const int warp = tid >> 5, lane = tid & 31;
    const int wm = warp & 1, wn = warp >> 1;
    const int g = lane >> 2, t4 = lane & 3;

    const int an0 = tid >> 3, an1 = (tid + 256) >> 3, af = tid & 7;
    const int koff = (af >> 1) * 8 + (af & 1);
    const float4 f4z = make_float4(0.f, 0.f, 0.f, 0.f);

    auto ldA = [&](int kc, float4& r0, float4& r1) {
        const float4* Asrc = (const float4*)g_x2;
        int kb = kc * 8;
        int gn0 = node0 + an0, gn1 = node0 + an1;
        r0 = (gn0 < NN) ? __ldg(&Asrc[(size_t)gn0 * 32 + kb + af]) : f4z;
        r1 = (gn1 < NN) ? __ldg(&Asrc[(size_t)gn1 * 32 + kb + af]) : f4z;
    };
    auto stA = [&](float4 r0, float4 r1) {
        uint32_t* Au = (uint32_t*)Apk;
        Au[an0 * 40 + koff + 0] = f2tf32(r0.x);
        Au[an0 * 40 + koff + 2] = f2tf32(r0.y);
        Au[an0 * 40 + koff + 4] = f2tf32(r0.z);
        Au[an0 * 40 + koff + 6] = f2tf32(r0.w);
        Au[an1 * 40 + koff + 0] = f2tf32(r1.x);
        Au[an1 * 40 + koff + 2] = f2tf32(r1.y);
        Au[an1 * 40 + koff + 4] = f2tf32(r1.z);
        Au[an1 * 40 + koff + 6] = f2tf32(r1.w);
    };
    auto ldW = [&](int kc, float4* w) {
        int kr0 = kc * 32;
        int p0 = 2 * warp, p1 = 2 * warp + 1;
        int k0 = (p0 >> 2) * 8 + (p0 & 3);
        int k1 = (p1 >> 2) * 8 + (p1 & 3);
        const float4* Wsrc = (lane < 16) ? (const float4*)Wl3 : (const float4*)Wr3;
        int cl = lane & 15;
        w[0] = __ldg(&Wsrc[(size_t)(kr0 + k0) * 16 + cl]);
        w[1] = __ldg(&Wsrc[(size_t)(kr0 + k0 + 4) * 16 + cl]);
        w[2] = __ldg(&Wsrc[(size_t)(kr0 + k1) * 16 + cl]);
        w[3] = __ldg(&Wsrc[(size_t)(kr0 + k1 + 4) * 16 + cl]);
    };
    auto stW = [&](const float4* w) {
        uint4* W4 = (uint4*)Wpk;
        #pragma unroll
        for (int q = 0; q < 2; q++) {
            int p = 2 * warp + q;
            float4 lo = w[2 * q], hi = w[2 * q + 1];
            W4[p * 66 + 2 * lane]     = make_uint4(f2tf32(lo.x), f2tf32(hi.x),
                                                   f2tf32(lo.y), f2tf32(hi.y));
            W4[p * 66 + 2 * lane + 1] = make_uint4(f2tf32(lo.z), f2tf32(hi.z),
                                                   f2tf32(lo.w), f2tf32(hi.w));
        }
    };

    float acc0[4][4], acc1[4][4];
    #pragma unroll
    for (int i = 0; i < 4; i++)
        #pragma unroll
        for (int j = 0; j < 4; j++) { acc0[i][j] = 0.f; acc1[i][j] = 0.f; }

    {
        float4 a0, a1, w0[4];
        ldA(0, a0, a1); ldW(0, w0);
        stA(a0, a1); stW(w0);
    }
    __syncthreads();

    const int C = wm * 32;
    for (int kc = 0; kc < 4; kc++) {
        float4 na0, na1, nw[4];
        if (kc < 3) { ldA(kc + 1, na0, na1); ldW(kc + 1, nw); }
        #pragma unroll
        for (int kk = 0; kk < 4; kk++) {
            int pbase = kk * 4 + t4;
            uint2 qa0 = Apk[(C + g)      * ASTR2 + pbase];
            uint2 qa1 = Apk[(C + g + 8)  * ASTR2 + pbase];
            uint2 qa2 = Apk[(C + g + 16) * ASTR2 + pbase];
            uint2 qa3 = Apk[(C + g + 24) * ASTR2 + pbase];
            #pragma unroll
            for (int nt = 0; nt < 4; nt++) {
                uint2 qb = Wpk[pbase * WSTR2 + wn * 32 + nt * 8 + g];
                mma_tf32(acc0[nt], qa0.x, qa1.x, qa0.y, qa1.y, qb.x, qb.y);
                mma_tf32(acc1[nt], qa2.x, qa3.x, qa2.y, qa3.y, qb.x, qb.y);
            }
        }
        __syncthreads();
        if (kc < 3) { stA(na0, na1); stW(nw); __syncthreads(); }
    }

    #pragma unroll
    for (int nt = 0; nt < 4; nt++) {
        int c = wn * 32 + nt * 8 + 2 * t4;
        float* dstbuf = (c < 64) ? g_p : g_q;
        int cc = c & 63;
        #pragma unroll
        for (int r = 0; r < 4; r++) {
            int gn = node0 + C + g + r * 8;
            if (gn >= NN) continue;
            float v0, v1;
            if (r == 0)      { v0 = acc0[nt][0]; v1 = acc0[nt][1]; }
            else if (r == 1) { v0 = acc0[nt][2]; v1 = acc0[nt][3]; }
            else if (r == 2) { v0 = acc1[nt][0]; v1 = acc1[nt][1]; }
            else             { v0 = acc1[nt][2]; v1 = acc1[nt][3]; }
            *(float2*)&dstbuf[(size_t)gn * DO + cc] = make_float2(v0, v1);
        }
    }
}

// ---- out_fused: gather(p) + gelu(+q+bl3) -> LN(64) -> @Wc + bcls ----
// warp per node; grid = ceil(NN/8), 256 threads.

__global__ __launch_bounds__(256) void out_fused(
    const float* __restrict__ bl3,
    const float* __restrict__ gc, const float* __restrict__ bc,
    const float* __restrict__ Wc, const float* __restrict__ bcls,
    float* __restrict__ out)
{
    __shared__ float Wcs[DO * NC];   // 10240 B
    __shared__ float bcs[NC];
    __shared__ float Vs[8][66];
    const int tid = threadIdx.x;
    const int warp = tid >> 5, lane = tid & 31;

    for (int i = tid; i < DO * NC; i += 256)
        Wcs[i] = __ldg(&Wc[i]);
    if (tid < NC) bcs[tid] = __ldg(&bcls[tid]);
    __syncthreads();

    int gn = blockIdx.x * 8 + warp;
    if (gn >= NN) return;

    // gather mean of p-neighbors (float2 slice per lane)
    int start = g_off[gn], deg = g_deg[gn];
    const int* es = g_esrc + start;
    const float2* p2 = (const float2*)g_p;
    float2 a0 = make_float2(0.f, 0.f), a1 = a0, a2 = a0, a3 = a0;
    int e = 0;
    for (; e + 4 <= deg; e += 4) {
        int s0 = __ldg(es + e),     s1 = __ldg(es + e + 1);
        int s2 = __ldg(es + e + 2), s3 = __ldg(es + e + 3);
        float2 v0 = __ldg(&p2[(size_t)s0 * 32 + lane]);
        float2 v1 = __ldg(&p2[(size_t)s1 * 32 + lane]);
        float2 v2 = __ldg(&p2[(size_t)s2 * 32 + lane]);
        float2 v3 = __ldg(&p2[(size_t)s3 * 32 + lane]);
        a0.x += v0.x; a0.y += v0.y;
        a1.x += v1.x; a1.y += v1.y;
        a2.x += v2.x; a2.y += v2.y;
        a3.x += v3.x; a3.y += v3.y;
    }
    for (; e < deg; e++) {
        int s0 = __ldg(es + e);
        float2 v0 = __ldg(&p2[(size_t)s0 * 32 + lane]);
        a0.x += v0.x; a0.y += v0.y;
    }
    float inv = 1.0f / fmaxf((float)deg, 1.0f);
    float agx = (a0.x + a1.x + a2.x + a3.x) * inv;
    float agy = (a0.y + a1.y + a2.y + a3.y) * inv;

    float2 q   = __ldg(&((const float2*)g_q)[(size_t)gn * 32 + lane]);
    float2 b3v = __ldg(&((const float2*)bl3)[lane]);
    float2 gcv = __ldg(&((const float2*)gc)[lane]);
    float2 bcv = __ldg(&((const float2*)bc)[lane]);

    float u0 = gelu_exact(agx + q.x + b3v.x);
    float u1 = gelu_exact(agy + q.y + b3v.y);
    float s1 = u0 + u1, s2 = u0 * u0 + u1 * u1;
    #pragma unroll
    for (int off = 16; off; off >>= 1) {
        s1 += __shfl_xor_sync(0xffffffffu, s1, off);
        s2 += __shfl_xor_sync(0xffffffffu, s2, off);
    }
    float mu = s1 * (1.0f / 64.0f);
    float var = s2 * (1.0f / 64.0f) - mu * mu;
    float rstd = rsqrtf(var + 1e-5f);
    Vs[warp][2 * lane]     = (u0 - mu) * rstd * gcv.x + bcv.x;
    Vs[warp][2 * lane + 1] = (u1 - mu) * rstd * gcv.y + bcv.y;
    __syncwarp();

    // classifier: lane -> col lane, and col lane+32 when <40
    float o1 = bcs[lane];
    float o2 = (lane < NC - 32) ? bcs[lane + 32] : 0.f;
    #pragma unroll 8
    for (int k = 0; k < DO; k++) {
        float vv = Vs[warp][k];
        o1 += vv * Wcs[k * NC + lane];
        if (lane < NC - 32) o2 += vv * Wcs[k * NC + lane + 32];
    }
    out[(size_t)gn * NC + lane] = o1;
    if (lane < NC - 32) out[(size_t)gn * NC + lane + 32] = o2;
}

// ---------------- launcher ----------------

extern "C" void kernel_launch(void* const* d_in, const int* in_sizes, int n_in,
                              void* d_out, int out_size)
{
    const float* x    = (const float*)d_in[0];
    const int*   ei   = (const int*)d_in[1];
    const float* Wl1  = (const float*)d_in[2];
    const float* bl1  = (const float*)d_in[3];
    const float* Wr1  = (const float*)d_in[4];
    const float* g1   = (const float*)d_in[5];
    const float* b1   = (const float*)d_in[6];
    const float* Wl2  = (const float*)d_in[7];
    const float* bl2  = (const float*)d_in[8];
    const float* Wr2  = (const float*)d_in[9];
    const float* g2   = (const float*)d_in[10];
    const float* b2   = (const float*)d_in[11];
    const float* Wl3  = (const float*)d_in[12];
    const float* bl3  = (const float*)d_in[13];
    const float* Wr3  = (const float*)d_in[14];
    const float* gc   = (const float*)d_in[15];
    const float* bc   = (const float*)d_in[16];
    const float* Wc   = (const float*)d_in[17];
    const float* bcls = (const float*)d_in[18];
    const int* src = ei;
    const int* dst = ei + NE;
    float* out = (float*)d_out;

    void *p_x1 = nullptr, *p_x2 = nullptr;
    cudaGetSymbolAddress(&p_x1, g_x1);
    cudaGetSymbolAddress(&p_x2, g_x2);

    const int nbn = (NN + 63) / 64;
    const int nbe = (NE + 255) / 256;
    const int nbw = ((NN * 32) + 255) / 256;   // one warp per node

    // CSR build
    zero_deg_cur<<<(NN + 255) / 256, 256>>>();
    count_deg<<<nbe, 256>>>(dst);
    scan_local<<<SCAN_B, SCAN_T>>>();
    scan_add2<<<(NN + 255) / 256, 128>>>();
    fill_edges<<<nbe, 256>>>(src, dst);

    // Layer 1
    gather128<<<nbw, 256>>>(x);
    sage_tc2<<<nbn, 256>>>(x, Wl1, bl1, Wr1, g1, b1, (float*)p_x1);

    // Layer 2
    gather128<<<nbw, 256>>>((const float*)p_x1);
    sage_tc2<<<nbn, 256>>>((const float*)p_x1, Wl2, bl2, Wr2, g2, b2, (float*)p_x2);

    // Layer 3: [p|q] = x2 @ [Wl3|Wr3], then fused gather+epilogue+classifier
    gemm_pq<<<nbn, 256>>>(Wl3, Wr3);
    out_fused<<<(NN + 7) / 8, 256>>>(bl3, gc, bc, Wc, bcls, out);
}

// round 14
// speedup vs baseline: 1.0004x; 1.0004x over previous
#include <cuda_runtime.h>
#include <math.h>
#include <stdint.h>

#define NN 50000
#define NE 800000
#define D  128
#define DO 64
#define NC 40
#define SCAN_T 512
#define SCAN_B ((NN + SCAN_T - 1) / SCAN_T)   // 98

#define ASTR2 20   // uint2 stride per node (paired A layout)
#define WSTR2 132  // uint2 stride per pair-row (paired W layout)
#define ARSTR 132  // uint32 stride per node (resident x2 tile)

// Scratch (device globals: no allocation allowed)
__device__ float g_agg[(size_t)NN * D];
__device__ float g_x1[(size_t)NN * D];
__device__ float g_p[(size_t)NN * DO];
__device__ float g_q[(size_t)NN * DO];
__device__ int   g_deg[NN];
__device__ int   g_off[NN];
__device__ int   g_cur[NN];
__device__ int   g_bsum[SCAN_B];
__device__ int   g_esrc[NE];

__device__ __forceinline__ float gelu_exact(float v) {
    return 0.5f * v * (1.0f + erff(v * 0.70710678118654752f));
}

__device__ __forceinline__ uint32_t f2tf32(float f) {
    uint32_t r;
    asm("cvt.rna.tf32.f32 %0, %1;" : "=r"(r) : "f"(f));
    return r;
}

__device__ __forceinline__ void mma_tf32(float* d,
    uint32_t a0, uint32_t a1, uint32_t a2, uint32_t a3,
    uint32_t b0, uint32_t b1)
{
    asm volatile(
        "mma.sync.aligned.m16n8k8.row.col.f32.tf32.tf32.f32 "
        "{%0,%1,%2,%3}, {%4,%5,%6,%7}, {%8,%9}, {%0,%1,%2,%3};"
        : "+f"(d[0]), "+f"(d[1]), "+f"(d[2]), "+f"(d[3])
        : "r"(a0), "r"(a1), "r"(a2), "r"(a3), "r"(b0), "r"(b1));
}

// ---------------- CSR build ----------------

__global__ void count_deg(const int* __restrict__ dst) {
    int e = blockIdx.x * blockDim.x + threadIdx.x;
    if (e < NE) atomicAdd(&g_deg[dst[e]], 1);
}

__global__ void scan_local() {
    __shared__ int s[SCAN_T];
    int t = threadIdx.x;
    int i = blockIdx.x * SCAN_T + t;
    int v = (i < NN) ? g_deg[i] : 0;
    s[t] = v;
    __syncthreads();
    #pragma unroll
    for (int off = 1; off < SCAN_T; off <<= 1) {
        int a = (t >= off) ? s[t - off] : 0;
        __syncthreads();
        s[t] += a;
        __syncthreads();
    }
    if (i < NN) g_off[i] = s[t] - v;
    if (t == SCAN_T - 1) g_bsum[blockIdx.x] = s[t];
}

// Each block redundantly scans the 98 block sums, then applies to its slice.
__global__ void scan_add2() {   // <<<(NN+255)/256, 128>>>, 2 elems/thread
    __shared__ int s[128];
    int t = threadIdx.x;
    int v = (t < SCAN_B) ? g_bsum[t] : 0;
    s[t] = v;
    __syncthreads();
    #pragma unroll
    for (int off = 1; off < 128; off <<= 1) {
        int a = (t >= off) ? s[t - off] : 0;
        __syncthreads();
        s[t] += a;
        __syncthreads();
    }
    int inc = s[t];
    __syncthreads();
    s[t] = inc - v;                               // exclusive
    __syncthreads();
    int i0 = blockIdx.x * 256 + t;
    int i1 = i0 + 128;
    if (i0 < NN) g_off[i0] += s[i0 / SCAN_T];
    if (i1 < NN) g_off[i1] += s[i1 / SCAN_T];
}

__global__ void fill_edges(const int* __restrict__ src, const int* __restrict__ dst) {
    int e = blockIdx.x * blockDim.x + threadIdx.x;
    if (e >= NE) return;
    int d = dst[e];
    int pos = g_off[d] + atomicAdd(&g_cur[d], 1);
    g_esrc[pos] = src[e];
}

// ---------------- gather mean-aggregation (warp/node, 4-way unrolled) --------

__global__ __launch_bounds__(256) void gather128(const float* __restrict__ x) {
    int gw = (blockIdx.x * blockDim.x + threadIdx.x) >> 5;
    int lane = threadIdx.x & 31;
    if (gw >= NN) return;
    int start = g_off[gw], deg = g_deg[gw];
    const int* es = g_esrc + start;
    const float4* x4 = (const float4*)x;
    float4 a0 = make_float4(0.f,0.f,0.f,0.f), a1 = a0, a2 = a0, a3 = a0;
    int e = 0;
    for (; e + 4 <= deg; e += 4) {
        int s0 = __ldg(es + e),     s1 = __ldg(es + e + 1);
        int s2 = __ldg(es + e + 2), s3 = __ldg(es + e + 3);
        float4 v0 = __ldg(&x4[(size_t)s0 * 32 + lane]);
        float4 v1 = __ldg(&x4[(size_t)s1 * 32 + lane]);
        float4 v2 = __ldg(&x4[(size_t)s2 * 32 + lane]);
        float4 v3 = __ldg(&x4[(size_t)s3 * 32 + lane]);
        a0.x += v0.x; a0.y += v0.y; a0.z += v0.z; a0.w += v0.w;
        a1.x += v1.x; a1.y += v1.y; a1.z += v1.z; a1.w += v1.w;
        a2.x += v2.x; a2.y += v2.y; a2.z += v2.z; a2.w += v2.w;
        a3.x += v3.x; a3.y += v3.y; a3.z += v3.z; a3.w += v3.w;
    }
    for (; e < deg; e++) {
        int s0 = __ldg(es + e);
        float4 v0 = __ldg(&x4[(size_t)s0 * 32 + lane]);
        a0.x += v0.x; a0.y += v0.y; a0.z += v0.z; a0.w += v0.w;
    }
    float inv = 1.0f / fmaxf((float)deg, 1.0f);
    float4 r;
    r.x = (a0.x + a1.x + a2.x + a3.x) * inv;
    r.y = (a0.y + a1.y + a2.y + a3.y) * inv;
    r.z = (a0.z + a1.z + a2.z + a3.z) * inv;
    r.w = (a0.w + a1.w + a2.w + a3.w) * inv;
    ((float4*)g_agg)[(size_t)gw * 32 + lane] = r;
}

// ---- SAGE block (layer 1): tf32 mma, 32x32 warp tiles, paired uint2 operands ----

__global__ __launch_bounds__(256, 2) void sage_tc2(
    const float* __restrict__ xin,
    const float* __restrict__ Wl, const float* __restrict__ bl,
    const float* __restrict__ Wr,
    const float* __restrict__ gma, const float* __restrict__ bta,
    float* __restrict__ xout)
{
    __shared__ uint2 Apk[64 * ASTR2];
    __shared__ uint2 Wpk[16 * WSTR2];
    __shared__ float sred[4][64][2];

    const int tid = threadIdx.x;
    const int node0 = blockIdx.x * 64;
    const int warp = tid >> 5, lane = tid & 31;
    const int wm = warp & 1, wn = warp >> 1;
    const int g = lane >> 2, t4 = lane & 3;

    const int an0 = tid >> 3, an1 = (tid + 256) >> 3, af = tid & 7;
    const int koff = (af >> 1) * 8 + (af & 1);
    const float4 f4z = make_float4(0.f, 0.f, 0.f, 0.f);

    auto ldA = [&](int kc, float4& r0, float4& r1) {
        const float4* Asrc = (kc < 4) ? (const float4*)g_agg : (const float4*)xin;
        int kb = (kc & 3) * 8;
        int gn0 = node0 + an0, gn1 = node0 + an1;
        r0 = (gn0 < NN) ? __ldg(&Asrc[(size_t)gn0 * 32 + kb + af]) : f4z;
        r1 = (gn1 < NN) ? __ldg(&Asrc[(size_t)gn1 * 32 + kb + af]) : f4z;
    };
    auto stA = [&](float4 r0, float4 r1) {
        uint32_t* Au = (uint32_t*)Apk;
        Au[an0 * 40 + koff + 0] = f2tf32(r0.x);
        Au[an0 * 40 + koff + 2] = f2tf32(r0.y);
        Au[an0 * 40 + koff + 4] = f2tf32(r0.z);
        Au[an0 * 40 + koff + 6] = f2tf32(r0.w);
        Au[an1 * 40 + koff + 0] = f2tf32(r1.x);
        Au[an1 * 40 + koff + 2] = f2tf32(r1.y);
        Au[an1 * 40 + koff + 4] = f2tf32(r1.z);
        Au[an1 * 40 + koff + 6] = f2tf32(r1.w);
    };
    auto ldW = [&](int kc, float4* w) {
        const float4* Wsrc = (kc < 4) ? (const float4*)Wl : (const float4*)Wr;
        int kr0 = (kc & 3) * 32;
        int p0 = 2 * warp, p1 = 2 * warp + 1;
        int k0 = (p0 >> 2) * 8 + (p0 & 3);
        int k1 = (p1 >> 2) * 8 + (p1 & 3);
        w[0] = __ldg(&Wsrc[(size_t)(kr0 + k0) * 32 + lane]);
        w[1] = __ldg(&Wsrc[(size_t)(kr0 + k0 + 4) * 32 + lane]);
        w[2] = __ldg(&Wsrc[(size_t)(kr0 + k1) * 32 + lane]);
        w[3] = __ldg(&Wsrc[(size_t)(kr0 + k1 + 4) * 32 + lane]);
    };
    auto stW = [&](const float4* w) {
        uint4* W4 = (uint4*)Wpk;
        #pragma unroll
        for (int q = 0; q < 2; q++) {
            int p = 2 * warp + q;
            float4 lo = w[2 * q], hi = w[2 * q + 1];
            W4[p * 66 + 2 * lane]     = make_uint4(f2tf32(lo.x), f2tf32(hi.x),
                                                   f2tf32(lo.y), f2tf32(hi.y));
            W4[p * 66 + 2 * lane + 1] = make_uint4(f2tf32(lo.z), f2tf32(hi.z),
                                                   f2tf32(lo.w), f2tf32(hi.w));
        }
    };

    float acc0[4][4], acc1[4][4];
    #pragma unroll
    for (int i = 0; i < 4; i++)
        #pragma unroll
        for (int j = 0; j < 4; j++) { acc0[i][j] = 0.f; acc1[i][j] = 0.f; }

    {
        float4 a0, a1, w0[4];
        ldA(0, a0, a1); ldW(0, w0);
        stA(a0, a1); stW(w0);
    }
    __syncthreads();

    const int C = wm * 32;
    for (int kc = 0; kc < 8; kc++) {
        float4 na0, na1, nw[4];
        if (kc < 7) { ldA(kc + 1, na0, na1); ldW(kc + 1, nw); }
        #pragma unroll
        for (int kk = 0; kk < 4; kk++) {
            int pbase = kk * 4 + t4;
            uint2 qa0 = Apk[(C + g)      * ASTR2 + pbase];
            uint2 qa1 = Apk[(C + g + 8)  * ASTR2 + pbase];
            uint2 qa2 = Apk[(C + g + 16) * ASTR2 + pbase];
            uint2 qa3 = Apk[(C + g + 24) * ASTR2 + pbase];
            #pragma unroll
            for (int nt = 0; nt < 4; nt++) {
                uint2 qb = Wpk[pbase * WSTR2 + wn * 32 + nt * 8 + g];
                mma_tf32(acc0[nt], qa0.x, qa1.x, qa0.y, qa1.y, qb.x, qb.y);
                mma_tf32(acc1[nt], qa2.x, qa3.x, qa2.y, qa3.y, qb.x, qb.y);
            }
        }
        __syncthreads();
        if (kc < 7) { stA(na0, na1); stW(nw); __syncthreads(); }
    }

    // ---- epilogue: + bl -> LN (128 cols) -> GELU -> + residual ----
    float s[4][2];
    #pragma unroll
    for (int r = 0; r < 4; r++) { s[r][0] = 0.f; s[r][1] = 0.f; }
    #pragma unroll
    for (int nt = 0; nt < 4; nt++) {
        int c = wn * 32 + nt * 8 + 2 * t4;
        float2 blv = *(const float2*)&bl[c];
        acc0[nt][0] += blv.x; acc0[nt][1] += blv.y;
        acc0[nt][2] += blv.x; acc0[nt][3] += blv.y;
        acc1[nt][0] += blv.x; acc1[nt][1] += blv.y;
        acc1[nt][2] += blv.x; acc1[nt][3] += blv.y;
        s[0][0] += acc0[nt][0] + acc0[nt][1];
        s[0][1] += acc0[nt][0]*acc0[nt][0] + acc0[nt][1]*acc0[nt][1];
        s[1][0] += acc0[nt][2] + acc0[nt][3];
        s[1][1] += acc0[nt][2]*acc0[nt][2] + acc0[nt][3]*acc0[nt][3];
        s[2][0] += acc1[nt][0] + acc1[nt][1];
        s[2][1] += acc1[nt][0]*acc1[nt][0] + acc1[nt][1]*acc1[nt][1];
        s[3][0] += acc1[nt][2] + acc1[nt][3];
        s[3][1] += acc1[nt][2]*acc1[nt][2] + acc1[nt][3]*acc1[nt][3];
    }
    #pragma unroll
    for (int off = 1; off <= 2; off <<= 1)
        #pragma unroll
        for (int r = 0; r < 4; r++) {
            s[r][0] += __shfl_xor_sync(0xffffffffu, s[r][0], off);
            s[r][1] += __shfl_xor_sync(0xffffffffu, s[r][1], off);
        }
    if (t4 == 0) {
        #pragma unroll
        for (int r = 0; r < 4; r++) {
            sred[wn][C + g + r * 8][0] = s[r][0];
            sred[wn][C + g + r * 8][1] = s[r][1];
        }
    }
    __syncthreads();

    float mu[4], rs[4];
    #pragma unroll
    for (int r = 0; r < 4; r++) {
        int row = C + g + r * 8;
        float S1 = sred[0][row][0] + sred[1][row][0] + sred[2][row][0] + sred[3][row][0];
        float S2 = sred[0][row][1] + sred[1][row][1] + sred[2][row][1] + sred[3][row][1];
        mu[r] = S1 * (1.0f / 128.0f);
        float var = S2 * (1.0f / 128.0f) - mu[r] * mu[r];
        rs[r] = rsqrtf(var + 1e-5f);
    }

    #pragma unroll
    for (int nt = 0; nt < 4; nt++) {
        int c = wn * 32 + nt * 8 + 2 * t4;
        float2 gv = *(const float2*)&gma[c];
        float2 bv = *(const float2*)&bta[c];
        #pragma unroll
        for (int r = 0; r < 4; r++) {
            int gn = node0 + C + g + r * 8;
            if (gn >= NN) continue;
            float v0, v1;
            if (r == 0)      { v0 = acc0[nt][0]; v1 = acc0[nt][1]; }
            else if (r == 1) { v0 = acc0[nt][2]; v1 = acc0[nt][3]; }
            else if (r == 2) { v0 = acc1[nt][0]; v1 = acc1[nt][1]; }
            else             { v0 = acc1[nt][2]; v1 = acc1[nt][3]; }
            float2 res = *(const float2*)&xin[(size_t)gn * D + c];
            float o0 = gelu_exact((v0 - mu[r]) * rs[r] * gv.x + bv.x) + res.x;
            float o1 = gelu_exact((v1 - mu[r]) * rs[r] * gv.y + bv.y) + res.y;
            *(float2*)&xout[(size_t)gn * D + c] = make_float2(o0, o1);
        }
    }
}

// ---- sage_pq (layer 2 + pq GEMM fused): same as sage_tc2, but x2 stays in
//      smem (tf32 Xr tile) and [p|q] = x2 @ [Wl3|Wr3] is computed in-kernel.
//      x2 never touches global memory.

__global__ __launch_bounds__(256, 2) void sage_pq(
    const float* __restrict__ xin,
    const float* __restrict__ Wl, const float* __restrict__ bl,
    const float* __restrict__ Wr,
    const float* __restrict__ gma, const float* __restrict__ bta,
    const float* __restrict__ Wl3, const float* __restrict__ Wr3)
{
    extern __shared__ uint32_t dsm[];
    uint2*    Apk  = (uint2*)dsm;                     // 2560 u32 = 10240 B
    uint2*    Wpk  = (uint2*)(dsm + 2560);            // 4224 u32 = 16896 B
    float*    sred = (float*)(dsm + 2560 + 4224);     //  512 u32 =  2048 B
    uint32_t* Xr   = dsm + 2560 + 4224 + 512;         // 8448 u32 = 33792 B

    const int tid = threadIdx.x;
    const int node0 = blockIdx.x * 64;
    const int warp = tid >> 5, lane = tid & 31;
    const int wm = warp & 1, wn = warp >> 1;
    const int g = lane >> 2, t4 = lane & 3;

    const int an0 = tid >> 3, an1 = (tid + 256) >> 3, af = tid & 7;
    const int koff = (af >> 1) * 8 + (af & 1);
    const float4 f4z = make_float4(0.f, 0.f, 0.f, 0.f);

    auto ldA = [&](int kc, float4& r0, float4& r1) {
        const float4* Asrc = (kc < 4) ? (const float4*)g_agg : (const float4*)xin;
        int kb = (kc & 3) * 8;
        int gn0 = node0 + an0, gn1 = node0 + an1;
        r0 = (gn0 < NN) ? __ldg(&Asrc[(size_t)gn0 * 32 + kb + af]) : f4z;
        r1 = (gn1 < NN) ? __ldg(&Asrc[(size_t)gn1 * 32 + kb + af]) : f4z;
    };
    auto stA = [&](float4 r0, float4 r1) {
        uint32_t* Au = (uint32_t*)Apk;
        Au[an0 * 40 + koff + 0] = f2tf32(r0.x);
        Au[an0 * 40 + koff + 2] = f2tf32(r0.y);
        Au[an0 * 40 + koff + 4] = f2tf32(r0.z);
        Au[an0 * 40 + koff + 6] = f2tf32(r0.w);
        Au[an1 * 40 + koff + 0] = f2tf32(r1.x);
        Au[an1 * 40 + koff + 2] = f2tf32(r1.y);
        Au[an1 * 40 + koff + 4] = f2tf32(r1.z);
        Au[an1 * 40 + koff + 6] = f2tf32(r1.w);
    };
    auto ldW = [&](int kc, float4* w) {
        const float4* Wsrc = (kc < 4) ? (const float4*)Wl : (const float4*)Wr;
        int kr0 = (kc & 3) * 32;
        int p0 = 2 * warp, p1 = 2 * warp + 1;
        int k0 = (p0 >> 2) * 8 + (p0 & 3);
        int k1 = (p1 >> 2) * 8 + (p1 & 3);
        w[0] = __ldg(&Wsrc[(size_t)(kr0 + k0) * 32 + lane]);
        w[1] = __ldg(&Wsrc[(size_t)(kr0 + k0 + 4) * 32 + lane]);
        w[2] = __ldg(&Wsrc[(size_t)(kr0 + k1) * 32 + lane]);
        w[3] = __ldg(&Wsrc[(size_t)(kr0 + k1 + 4) * 32 + lane]);
    };
    // pq weight chunks: cols 0..63 from Wl3, 64..127 from Wr3 (both [128][64])
    auto ldW3 = [&](int kc, float4* w) {
        int kr0 = kc * 32;
        int p0 = 2 * warp, p1 = 2 * warp + 1;
        int k0 = (p0 >> 2) * 8 + (p0 & 3);
        int k1 = (p1 >> 2) * 8 + (p1 & 3);
        const float4* Wsrc = (lane < 16) ? (const float4*)Wl3 : (const float4*)Wr3;
        int cl = lane & 15;
        w[0] = __ldg(&Wsrc[(size_t)(kr0 + k0) * 16 + cl]);
        w[1] = __ldg(&Wsrc[(size_t)(kr0 + k0 + 4) * 16 + cl]);
        w[2] = __ldg(&Wsrc[(size_t)(kr0 + k1) * 16 + cl]);
        w[3] = __ldg(&Wsrc[(size_t)(kr0 + k1 + 4) * 16 + cl]);
    };
    auto stW = [&](const float4* w) {
        uint4* W4 = (uint4*)Wpk;
        #pragma unroll
        for (int q = 0; q < 2; q++) {
            int p = 2 * warp + q;
            float4 lo = w[2 * q], hi = w[2 * q + 1];
            W4[p * 66 + 2 * lane]     = make_uint4(f2tf32(lo.x), f2tf32(hi.x),
                                                   f2tf32(lo.y), f2tf32(hi.y));
            W4[p * 66 + 2 * lane + 1] = make_uint4(f2tf32(lo.z), f2tf32(hi.z),
                                                   f2tf32(lo.w), f2tf32(hi.w));
        }
    };

    float acc0[4][4], acc1[4][4];
    #pragma unroll
    for (int i = 0; i < 4; i++)
        #pragma unroll
        for (int j = 0; j < 4; j++) { acc0[i][j] = 0.f; acc1[i][j] = 0.f; }

    {
        float4 a0, a1, w0[4];
        ldA(0, a0, a1); ldW(0, w0);
        stA(a0, a1); stW(w0);
    }
    __syncthreads();

    const int C = wm * 32;
    for (int kc = 0; kc < 8; kc++) {
        float4 na0, na1, nw[4];
        if (kc < 7) { ldA(kc + 1, na0, na1); ldW(kc + 1, nw); }
        #pragma unroll
        for (int kk = 0; kk < 4; kk++) {
            int pbase = kk * 4 + t4;
            uint2 qa0 = Apk[(C + g)      * ASTR2 + pbase];
            uint2 qa1 = Apk[(C + g + 8)  * ASTR2 + pbase];
            uint2 qa2 = Apk[(C + g + 16) * ASTR2 + pbase];
            uint2 qa3 = Apk[(C + g + 24) * ASTR2 + pbase];
            #pragma unroll
            for (int nt = 0; nt < 4; nt++) {
                uint2 qb = Wpk[pbase * WSTR2 + wn * 32 + nt * 8 + g];
                mma_tf32(acc0[nt], qa0.x, qa1.x, qa0.y, qa1.y, qb.x, qb.y);
                mma_tf32(acc1[nt], qa2.x, qa3.x, qa2.y, qa3.y, qb.x, qb.y);
            }
        }
        __syncthreads();
        if (kc < 7) { stA(na0, na1); stW(nw); __syncthreads(); }
    }

    // ---- epilogue: + bl -> LN -> GELU -> + residual -> Xr (tf32, smem only) ----
    float s[4][2];
    #pragma unroll
    for (int r = 0; r < 4; r++) { s[r][0] = 0.f; s[r][1] = 0.f; }
    #pragma unroll
    for (int nt = 0; nt < 4; nt++) {
        int c = wn * 32 + nt * 8 + 2 * t4;
        float2 blv = *(const float2*)&bl[c];
        acc0[nt][0] += blv.x; acc0[nt][1] += blv.y;
        acc0[nt][2] += blv.x; acc0[nt][3] += blv.y;
        acc1[nt][0] += blv.x; acc1[nt][1] += blv.y;
        acc1[nt][2] += blv.x; acc1[nt][3] += blv.y;
        s[0][0] += acc0[nt][0] + acc0[nt][1];
        s[0][1] += acc0[nt][0]*acc0[nt][0] + acc0[nt][1]*acc0[nt][1];
        s[1][0] += acc0[nt][2] + acc0[nt][3];
        s[1][1] += acc0[nt][2]*acc0[nt][2] + acc0[nt][3]*acc0[nt][3];
        s[2][0] += acc1[nt][0] + acc1[nt][1];
        s[2][1] += acc1[nt][0]*acc1[nt][0] + acc1[nt][1]*acc1[nt][1];
        s[3][0] += acc1[nt][2] + acc1[nt][3];
        s[3][1] += acc1[nt][2]*acc1[nt][2] + acc1[nt][3]*acc1[nt][3];
    }
    #pragma unroll
    for (int off = 1; off <= 2; off <<= 1)
        #pragma unroll
        for (int r = 0; r < 4; r++) {
            s[r][0] += __shfl_xor_sync(0xffffffffu, s[r][0], off);
            s[r][1] += __shfl_xor_sync(0xffffffffu, s[r][1], off);
        }
    if (t4 == 0) {
        #pragma unroll
        for (int r = 0; r < 4; r++) {
            sred[(wn * 64 + C + g + r * 8) * 2 + 0] = s[r][0];
            sred[(wn * 64 + C + g + r * 8) * 2 + 1] = s[r][1];
        }
    }
    __syncthreads();

    float mu[4], rs[4];
    #pragma unroll
    for (int r = 0; r < 4; r++) {
        int row = C + g + r * 8;
        float S1 = sred[(0 * 64 + row) * 2] + sred[(1 * 64 + row) * 2]
                 + sred[(2 * 64 + row) * 2] + sred[(3 * 64 + row) * 2];
        float S2 = sred[(0 * 64 + row) * 2 + 1] + sred[(1 * 64 + row) * 2 + 1]
                 + sred[(2 * 64 + row) * 2 + 1] + sred[(3 * 64 + row) * 2 + 1];
        mu[r] = S1 * (1.0f / 128.0f);
        float var = S2 * (1.0f / 128.0f) - mu[r] * mu[r];
        rs[r] = rsqrtf(var + 1e-5f);
    }

    #pragma unroll
    for (int nt = 0; nt < 4; nt++) {
        int c = wn * 32 + nt * 8 + 2 * t4;
        float2 gv = *(const float2*)&gma[c];
        float2 bv = *(const float2*)&bta[c];
        #pragma unroll
        for (int r = 0; r < 4; r++) {
            int row = C + g + r * 8;
            int gn = node0 + row;
            float v0, v1;
            if (r == 0)      { v0 = acc0[nt][0]; v1 = acc0[nt][1]; }
            else if (r == 1) { v0 = acc0[nt][2]; v1 = acc0[nt][3]; }
            else if (r == 2) { v0 = acc1[nt][0]; v1 = acc1[nt][1]; }
            else             { v0 = acc1[nt][2]; v1 = acc1[nt][3]; }
            float o0 = 0.f, o1 = 0.f;
            if (gn < NN) {
                float2 res = *(const float2*)&xin[(size_t)gn * D + c];
                o0 = gelu_exact((v0 - mu[r]) * rs[r] * gv.x + bv.x) + res.x;
                o1 = gelu_exact((v1 - mu[r]) * rs[r] * gv.y + bv.y) + res.y;
            }
            Xr[row * ARSTR + c]     = f2tf32(o0);
            Xr[row * ARSTR + c + 1] = f2tf32(o1);
        }
    }
    __syncthreads();   // Xr complete; Wpk free for reuse

    // ---- pq GEMM: [p|q] = x2 @ [Wl3|Wr3], K=128 from resident Xr ----
    #pragma unroll
    for (int i = 0; i < 4; i++)
        #pragma unroll
        for (int j = 0; j < 4; j++) { acc0[i][j] = 0.f; acc1[i][j] = 0.f; }

    {
        float4 w0[4];
        ldW3(0, w0);
        stW(w0);
    }
    __syncthreads();

    for (int kc = 0; kc < 4; kc++) {
        float4 nw[4];
        if (kc < 3) ldW3(kc + 1, nw);
        #pragma unroll
        for (int kk = 0; kk < 4; kk++) {
            int kb = kc * 32 + kk * 8 + t4;
            uint32_t a00 = Xr[(C + g)      * ARSTR + kb];
            uint32_t a10 = Xr[(C + g + 8)  * ARSTR + kb];
            uint32_t a20 = Xr[(C + g + 16) * ARSTR + kb];
            uint32_t a30 = Xr[(C + g + 24) * ARSTR + kb];
            uint32_t a01 = Xr[(C + g)      * ARSTR + kb + 4];
            uint32_t a11 = Xr[(C + g + 8)  * ARSTR + kb + 4];
            uint32_t a21 = Xr[(C + g + 16) * ARSTR + kb + 4];
            uint32_t a31 = Xr[(C + g + 24) * ARSTR + kb + 4];
            #pragma unroll
            for (int nt = 0; nt < 4; nt++) {
                uint2 qb = Wpk[(kk * 4 + t4) * WSTR2 + wn * 32 + nt * 8 + g];
                mma_tf32(acc0[nt], a00, a10, a01, a11, qb.x, qb.y);
                mma_tf32(acc1[nt], a20, a30, a21, a31, qb.x, qb.y);
            }
        }
        __syncthreads();
        if (kc < 3) { stW(nw); __syncthreads(); }
    }

    #pragma unroll
    for (int nt = 0; nt < 4; nt++) {
        int c = wn * 32 + nt * 8 + 2 * t4;
        float* dstbuf = (c < 64) ? g_p : g_q;
        int cc = c & 63;
        #pragma unroll
        for (int r = 0; r < 4; r++) {
            int gn = node0 + C + g + r * 8;
            if (gn >= NN) continue;
            float v0, v1;
            if (r == 0)      { v0 = acc0[nt][0]; v1 = acc0[nt][1]; }
            else if (r == 1) { v0 = acc0[nt][2]; v1 = acc0[nt][3]; }
            else if (r == 2) { v0 = acc1[nt][0]; v1 = acc1[nt][1]; }
            else             { v0 = acc1[nt][2]; v1 = acc1[nt][3]; }
            *(float2*)&dstbuf[(size_t)gn * DO + cc] = make_float2(v0, v1);
        }
    }
}

// ---- out_fused64: gather(p) + gelu(+q+bl3) -> LN(64) -> @Wc + bcls ----
// 64-node tile per block (8 warps x 8 nodes) so Wc staging is amortized.

__global__ __launch_bounds__(256) void out_fused64(
    const float* __restrict__ bl3,
    const float* __restrict__ gc, const float* __restrict__ bc,
    const float* __restrict__ Wc, const float* __restrict__ bcls,
    float* __restrict__ out)
{
    __shared__ float Wcs[DO * NC];   // 10240 B
    __shared__ float bcs[NC];
    __shared__ float Vs[64 * 66];    // 16896 B
    const int tid = threadIdx.x;
    const int node0 = blockIdx.x * 64;
    const int warp = tid >> 5, lane = tid & 31;

    for (int i = tid; i < DO * NC; i += 256)
        Wcs[i] = __ldg(&Wc[i]);
    if (tid < NC) bcs[tid] = __ldg(&bcls[tid]);

    float2 b3v = __ldg(&((const float2*)bl3)[lane]);
    float2 gcv = __ldg(&((const float2*)gc)[lane]);
    float2 bcv = __ldg(&((const float2*)bc)[lane]);
    const float2* p2 = (const float2*)g_p;

    for (int nn = 0; nn < 8; nn++) {
        int ln = warp * 8 + nn;
        int gn = node0 + ln;
        if (gn >= NN) break;
        int start = g_off[gn], deg = g_deg[gn];
        const int* es = g_esrc + start;
        float2 a0 = make_float2(0.f, 0.f), a1 = a0, a2 = a0, a3 = a0;
        int e = 0;
        for (; e + 4 <= deg; e += 4) {
            int s0 = __ldg(es + e),     s1 = __ldg(es + e + 1);
            int s2 = __ldg(es + e + 2), s3 = __ldg(es + e + 3);
            float2 v0 = __ldg(&p2[(size_t)s0 * 32 + lane]);
            float2 v1 = __ldg(&p2[(size_t)s1 * 32 + lane]);
            float2 v2 = __ldg(&p2[(size_t)s2 * 32 + lane]);
            float2 v3 = __ldg(&p2[(size_t)s3 * 32 + lane]);
            a0.x += v0.x; a0.y += v0.y;
            a1.x += v1.x; a1.y += v1.y;
            a2.x += v2.x; a2.y += v2.y;
            a3.x += v3.x; a3.y += v3.y;
        }
        for (; e < deg; e++) {
            int s0 = __ldg(es + e);
            float2 v0 = __ldg(&p2[(size_t)s0 * 32 + lane]);
            a0.x += v0.x; a0.y += v0.y;
        }
        float inv = 1.0f / fmaxf((float)deg, 1.0f);
        float agx = (a0.x + a1.x + a2.x + a3.x) * inv;
        float agy = (a0.y + a1.y + a2.y + a3.y) * inv;

        float2 q = __ldg(&((const float2*)g_q)[(size_t)gn * 32 + lane]);
        float u0 = gelu_exact(agx + q.x + b3v.x);
        float u1 = gelu_exact(agy + q.y + b3v.y);
        float s1 = u0 + u1, s2 = u0 * u0 + u1 * u1;
        #pragma unroll
        for (int off = 16; off; off >>= 1) {
            s1 += __shfl_xor_sync(0xffffffffu, s1, off);
            s2 += __shfl_xor_sync(0xffffffffu, s2, off);
        }
        float mu = s1 * (1.0f / 64.0f);
        float var = s2 * (1.0f / 64.0f) - mu * mu;
        float rstd = rsqrtf(var + 1e-5f);
        Vs[ln * 66 + 2 * lane]     = (u0 - mu) * rstd * gcv.x + bcv.x;
        Vs[ln * 66 + 2 * lane + 1] = (u1 - mu) * rstd * gcv.y + bcv.y;
    }
    __syncthreads();

    int n = tid >> 2, cg = (tid & 3) * 10;
    int gn = node0 + n;
    if (gn >= NN) return;
    float o[10];
    #pragma unroll
    for (int j = 0; j < 10; j++) o[j] = bcs[cg + j];
    #pragma unroll 8
    for (int k = 0; k < DO; k++) {
        float vv = Vs[n * 66 + k];
        #pragma unroll
        for (int j = 0; j < 10; j++)
            o[j] += vv * Wcs[k * NC + cg + j];
    }
    #pragma unroll
    for (int j = 0; j < 10; j++)
        out[(size_t)gn * NC + cg + j] = o[j];
}

// ---------------- launcher ----------------

extern "C" void kernel_launch(void* const* d_in, const int* in_sizes, int n_in,
                              void* d_out, int out_size)
{
    const float* x    = (const float*)d_in[0];
    const int*   ei   = (const int*)d_in[1];
    const float* Wl1  = (const float*)d_in[2];
    const float* bl1  = (const float*)d_in[3];
    const float* Wr1  = (const float*)d_in[4];
    const float* g1   = (const float*)d_in[5];
    const float* b1   = (const float*)d_in[6];
    const float* Wl2  = (const float*)d_in[7];
    const float* bl2  = (const float*)d_in[8];
    const float* Wr2  = (const float*)d_in[9];
    const float* g2   = (const float*)d_in[10];
    const float* b2   = (const float*)d_in[11];
    const float* Wl3  = (const float*)d_in[12];
    const float* bl3  = (const float*)d_in[13];
    const float* Wr3  = (const float*)d_in[14];
    const float* gc   = (const float*)d_in[15];
    const float* bc   = (const float*)d_in[16];
    const float* Wc   = (const float*)d_in[17];
    const float* bcls = (const float*)d_in[18];
    const int* src = ei;
    const int* dst = ei + NE;
    float* out = (float*)d_out;

    void *p_x1 = nullptr, *p_deg = nullptr, *p_cur = nullptr;
    cudaGetSymbolAddress(&p_x1, g_x1);
    cudaGetSymbolAddress(&p_deg, g_deg);
    cudaGetSymbolAddress(&p_cur, g_cur);

    const int smem_pq = (2560 + 4224 + 512 + 8448) * 4;   // 62976 B
    cudaFuncSetAttribute(sage_pq, cudaFuncAttributeMaxDynamicSharedMemorySize, smem_pq);

    const int nbn = (NN + 63) / 64;
    const int nbe = (NE + 255) / 256;
    const int nbw = ((NN * 32) + 255) / 256;   // one warp per node

    // CSR build
    cudaMemsetAsync(p_deg, 0, (size_t)NN * sizeof(int));
    cudaMemsetAsync(p_cur, 0, (size_t)NN * sizeof(int));
    count_deg<<<nbe, 256>>>(dst);
    scan_local<<<SCAN_B, SCAN_T>>>();
    scan_add2<<<(NN + 255) / 256, 128>>>();
    fill_edges<<<nbe, 256>>>(src, dst);

    // Layer 1
    gather128<<<nbw, 256>>>(x);
    sage_tc2<<<nbn, 256>>>(x, Wl1, bl1, Wr1, g1, b1, (float*)p_x1);

    // Layer 2 + pq GEMM fused (x2 never hits global memory)
    gather128<<<nbw, 256>>>((const float*)p_x1);
    sage_pq<<<nbn, 256, smem_pq>>>((const float*)p_x1, Wl2, bl2, Wr2, g2, b2, Wl3, Wr3);

    // Layer 3 tail: fused gather(p) + epilogue + classifier
    out_fused64<<<nbn, 256>>>(bl3, gc, bc, Wc, bcls, out);
}

// round 15
// speedup vs baseline: 1.0060x; 1.0056x over previous
#include <cuda_runtime.h>
#include <math.h>
#include <stdint.h>

#define NN 50000
#define NE 800000
#define D  128
#define DO 64
#define NC 40
#define SCAN_T 512
#define SCAN_B ((NN + SCAN_T - 1) / SCAN_T)   // 98

#define ASTR2 20   // uint2 stride per node (paired A layout)
#define WSTR2 132  // uint2 stride per pair-row (paired W layout)
#define ARSTR 132  // uint32 stride per node (resident x2 tile)
#define BUFU  6784 // u32 per operand buffer: A(2560) + W(4224)

// Scratch (device globals: no allocation allowed)
__device__ float g_agg[(size_t)NN * D];
__device__ float g_x1[(size_t)NN * D];
__device__ float g_p[(size_t)NN * DO];
__device__ float g_q[(size_t)NN * DO];
__device__ int   g_deg[NN];
__device__ int   g_off[NN];
__device__ int   g_off2[NN];
__device__ int   g_bsum[SCAN_B];
__device__ int   g_esrc[NE];

__device__ __forceinline__ float gelu_exact(float v) {
    return 0.5f * v * (1.0f + erff(v * 0.70710678118654752f));
}

__device__ __forceinline__ uint32_t f2tf32(float f) {
    uint32_t r;
    asm("cvt.rna.tf32.f32 %0, %1;" : "=r"(r) : "f"(f));
    return r;
}

__device__ __forceinline__ void mma_tf32(float* d,
    uint32_t a0, uint32_t a1, uint32_t a2, uint32_t a3,
    uint32_t b0, uint32_t b1)
{
    asm volatile(
        "mma.sync.aligned.m16n8k8.row.col.f32.tf32.tf32.f32 "
        "{%0,%1,%2,%3}, {%4,%5,%6,%7}, {%8,%9}, {%0,%1,%2,%3};"
        : "+f"(d[0]), "+f"(d[1]), "+f"(d[2]), "+f"(d[3])
        : "r"(a0), "r"(a1), "r"(a2), "r"(a3), "r"(b0), "r"(b1));
}

// ---------------- CSR build ----------------

__global__ void count_deg(const int* __restrict__ dst) {
    int e = blockIdx.x * blockDim.x + threadIdx.x;
    if (e < NE) atomicAdd(&g_deg[dst[e]], 1);
}

__global__ void scan_local() {
    __shared__ int s[SCAN_T];
    int t = threadIdx.x;
    int i = blockIdx.x * SCAN_T + t;
    int v = (i < NN) ? g_deg[i] : 0;
    s[t] = v;
    __syncthreads();
    #pragma unroll
    for (int off = 1; off < SCAN_T; off <<= 1) {
        int a = (t >= off) ? s[t - off] : 0;
        __syncthreads();
        s[t] += a;
        __syncthreads();
    }
    if (i < NN) g_off[i] = s[t] - v;
    if (t == SCAN_T - 1) g_bsum[blockIdx.x] = s[t];
}

// Each block redundantly scans the 98 block sums, applies to its slice,
// and writes BOTH g_off (stable) and g_off2 (bumped by fill_edges).
__global__ void scan_add2() {   // <<<(NN+255)/256, 128>>>, 2 elems/thread
    __shared__ int s[128];
    int t = threadIdx.x;
    int v = (t < SCAN_B) ? g_bsum[t] : 0;
    s[t] = v;
    __syncthreads();
    #pragma unroll
    for (int off = 1; off < 128; off <<= 1) {
        int a = (t >= off) ? s[t - off] : 0;
        __syncthreads();
        s[t] += a;
        __syncthreads();
    }
    int inc = s[t];
    __syncthreads();
    s[t] = inc - v;                               // exclusive
    __syncthreads();
    int i0 = blockIdx.x * 256 + t;
    int i1 = i0 + 128;
    if (i0 < NN) { int o = g_off[i0] + s[i0 / SCAN_T]; g_off[i0] = o; g_off2[i0] = o; }
    if (i1 < NN) { int o = g_off[i1] + s[i1 / SCAN_T]; g_off[i1] = o; g_off2[i1] = o; }
}

__global__ void fill_edges(const int* __restrict__ src, const int* __restrict__ dst) {
    int e = blockIdx.x * blockDim.x + threadIdx.x;
    if (e >= NE) return;
    int d = dst[e];
    int pos = atomicAdd(&g_off2[d], 1);
    g_esrc[pos] = src[e];
}

// ---------------- gather mean-aggregation (warp/node, 4-way unrolled) --------

__global__ __launch_bounds__(256) void gather128(const float* __restrict__ x) {
    int gw = (blockIdx.x * blockDim.x + threadIdx.x) >> 5;
    int lane = threadIdx.x & 31;
    if (gw >= NN) return;
    int start = g_off[gw], deg = g_deg[gw];
    const int* es = g_esrc + start;
    const float4* x4 = (const float4*)x;
    float4 a0 = make_float4(0.f,0.f,0.f,0.f), a1 = a0, a2 = a0, a3 = a0;
    int e = 0;
    for (; e + 4 <= deg; e += 4) {
        int s0 = __ldg(es + e),     s1 = __ldg(es + e + 1);
        int s2 = __ldg(es + e + 2), s3 = __ldg(es + e + 3);
        float4 v0 = __ldg(&x4[(size_t)s0 * 32 + lane]);
        float4 v1 = __ldg(&x4[(size_t)s1 * 32 + lane]);
        float4 v2 = __ldg(&x4[(size_t)s2 * 32 + lane]);
        float4 v3 = __ldg(&x4[(size_t)s3 * 32 + lane]);
        a0.x += v0.x; a0.y += v0.y; a0.z += v0.z; a0.w += v0.w;
        a1.x += v1.x; a1.y += v1.y; a1.z += v1.z; a1.w += v1.w;
        a2.x += v2.x; a2.y += v2.y; a2.z += v2.z; a2.w += v2.w;
        a3.x += v3.x; a3.y += v3.y; a3.z += v3.z; a3.w += v3.w;
    }
    for (; e < deg; e++) {
        int s0 = __ldg(es + e);
        float4 v0 = __ldg(&x4[(size_t)s0 * 32 + lane]);
        a0.x += v0.x; a0.y += v0.y; a0.z += v0.z; a0.w += v0.w;
    }
    float inv = 1.0f / fmaxf((float)deg, 1.0f);
    float4 r;
    r.x = (a0.x + a1.x + a2.x + a3.x) * inv;
    r.y = (a0.y + a1.y + a2.y + a3.y) * inv;
    r.z = (a0.z + a1.z + a2.z + a3.z) * inv;
    r.w = (a0.w + a1.w + a2.w + a3.w) * inv;
    ((float4*)g_agg)[(size_t)gw * 32 + lane] = r;
}

// ---- SAGE block (layer 1): tf32 mma, double-buffered operand staging ----
// Buffer layout (u32): [A: 2560][W: 4224] per buffer; 1 __syncthreads per chunk.

__global__ __launch_bounds__(256, 2) void sage_tc2(
    const float* __restrict__ xin,
    const float* __restrict__ Wl, const float* __restrict__ bl,
    const float* __restrict__ Wr,
    const float* __restrict__ gma, const float* __restrict__ bta,
    float* __restrict__ xout)
{
    extern __shared__ uint32_t dsm[];
    uint32_t* buf0 = dsm;
    uint32_t* buf1 = dsm + BUFU;
    float*    sred = (float*)(dsm + 2 * BUFU);    // 512 floats

    const int tid = threadIdx.x;
    const int node0 = blockIdx.x * 64;
    const int warp = tid >> 5, lane = tid & 31;
    const int wm = warp & 1, wn = warp >> 1;
    const int g = lane >> 2, t4 = lane & 3;

    const int an0 = tid >> 3, an1 = (tid + 256) >> 3, af = tid & 7;
    const int koff = (af >> 1) * 8 + (af & 1);
    const float4 f4z = make_float4(0.f, 0.f, 0.f, 0.f);

    auto ldA = [&](int kc, float4& r0, float4& r1) {
        const float4* Asrc = (kc < 4) ? (const float4*)g_agg : (const float4*)xin;
        int kb = (kc & 3) * 8;
        int gn0 = node0 + an0, gn1 = node0 + an1;
        r0 = (gn0 < NN) ? __ldg(&Asrc[(size_t)gn0 * 32 + kb + af]) : f4z;
        r1 = (gn1 < NN) ? __ldg(&Asrc[(size_t)gn1 * 32 + kb + af]) : f4z;
    };
    auto stA = [&](uint32_t* B, float4 r0, float4 r1) {
        B[an0 * 40 + koff + 0] = f2tf32(r0.x);
        B[an0 * 40 + koff + 2] = f2tf32(r0.y);
        B[an0 * 40 + koff + 4] = f2tf32(r0.z);
        B[an0 * 40 + koff + 6] = f2tf32(r0.w);
        B[an1 * 40 + koff + 0] = f2tf32(r1.x);
        B[an1 * 40 + koff + 2] = f2tf32(r1.y);
        B[an1 * 40 + koff + 4] = f2tf32(r1.z);
        B[an1 * 40 + koff + 6] = f2tf32(r1.w);
    };
    auto ldW = [&](int kc, float4* w) {
        const float4* Wsrc = (kc < 4) ? (const float4*)Wl : (const float4*)Wr;
        int kr0 = (kc & 3) * 32;
        int p0 = 2 * warp, p1 = 2 * warp + 1;
        int k0 = (p0 >> 2) * 8 + (p0 & 3);
        int k1 = (p1 >> 2) * 8 + (p1 & 3);
        w[0] = __ldg(&Wsrc[(size_t)(kr0 + k0) * 32 + lane]);
        w[1] = __ldg(&Wsrc[(size_t)(kr0 + k0 + 4) * 32 + lane]);
        w[2] = __ldg(&Wsrc[(size_t)(kr0 + k1) * 32 + lane]);
        w[3] = __ldg(&Wsrc[(size_t)(kr0 + k1 + 4) * 32 + lane]);
    };
    auto stW = [&](uint32_t* B, const float4* w) {
        uint4* W4 = (uint4*)(B + 2560);
        #pragma unroll
        for (int q = 0; q < 2; q++) {
            int p = 2 * warp + q;
            float4 lo = w[2 * q], hi = w[2 * q + 1];
            W4[p * 66 + 2 * lane]     = make_uint4(f2tf32(lo.x), f2tf32(hi.x),
                                                   f2tf32(lo.y), f2tf32(hi.y));
            W4[p * 66 + 2 * lane + 1] = make_uint4(f2tf32(lo.z), f2tf32(hi.z),
                                                   f2tf32(lo.w), f2tf32(hi.w));
        }
    };

    float acc0[4][4], acc1[4][4];
    #pragma unroll
    for (int i = 0; i < 4; i++)
        #pragma unroll
        for (int j = 0; j < 4; j++) { acc0[i][j] = 0.f; acc1[i][j] = 0.f; }

    {
        float4 a0, a1, w0[4];
        ldA(0, a0, a1); ldW(0, w0);
        stA(buf0, a0, a1); stW(buf0, w0);
    }
    __syncthreads();

    const int C = wm * 32;
    for (int kc = 0; kc < 8; kc++) {
        float4 na0, na1, nw[4];
        if (kc < 7) { ldA(kc + 1, na0, na1); ldW(kc + 1, nw); }
        uint32_t* B = (kc & 1) ? buf1 : buf0;
        const uint2* Apk = (const uint2*)B;
        const uint2* Wpk = (const uint2*)(B + 2560);
        #pragma unroll
        for (int kk = 0; kk < 4; kk++) {
            int pbase = kk * 4 + t4;
            uint2 qa0 = Apk[(C + g)      * ASTR2 + pbase];
            uint2 qa1 = Apk[(C + g + 8)  * ASTR2 + pbase];
            uint2 qa2 = Apk[(C + g + 16) * ASTR2 + pbase];
            uint2 qa3 = Apk[(C + g + 24) * ASTR2 + pbase];
            #pragma unroll
            for (int nt = 0; nt < 4; nt++) {
                uint2 qb = Wpk[pbase * WSTR2 + wn * 32 + nt * 8 + g];
                mma_tf32(acc0[nt], qa0.x, qa1.x, qa0.y, qa1.y, qb.x, qb.y);
                mma_tf32(acc1[nt], qa2.x, qa3.x, qa2.y, qa3.y, qb.x, qb.y);
            }
        }
        if (kc < 7) {
            uint32_t* Bn = (kc & 1) ? buf0 : buf1;
            stA(Bn, na0, na1); stW(Bn, nw);
            __syncthreads();
        }
    }

    // ---- epilogue: + bl -> LN (128 cols) -> GELU -> + residual ----
    float s[4][2];
    #pragma unroll
    for (int r = 0; r < 4; r++) { s[r][0] = 0.f; s[r][1] = 0.f; }
    #pragma unroll
    for (int nt = 0; nt < 4; nt++) {
        int c = wn * 32 + nt * 8 + 2 * t4;
        float2 blv = *(const float2*)&bl[c];
        acc0[nt][0] += blv.x; acc0[nt][1] += blv.y;
        acc0[nt][2] += blv.x; acc0[nt][3] += blv.y;
        acc1[nt][0] += blv.x; acc1[nt][1] += blv.y;
        acc1[nt][2] += blv.x; acc1[nt][3] += blv.y;
        s[0][0] += acc0[nt][0] + acc0[nt][1];
        s[0][1] += acc0[nt][0]*acc0[nt][0] + acc0[nt][1]*acc0[nt][1];
        s[1][0] += acc0[nt][2] + acc0[nt][3];
        s[1][1] += acc0[nt][2]*acc0[nt][2] + acc0[nt][3]*acc0[nt][3];
        s[2][0] += acc1[nt][0] + acc1[nt][1];
        s[2][1] += acc1[nt][0]*acc1[nt][0] + acc1[nt][1]*acc1[nt][1];
        s[3][0] += acc1[nt][2] + acc1[nt][3];
        s[3][1] += acc1[nt][2]*acc1[nt][2] + acc1[nt][3]*acc1[nt][3];
    }
    #pragma unroll
    for (int off = 1; off <= 2; off <<= 1)
        #pragma unroll
        for (int r = 0; r < 4; r++) {
            s[r][0] += __shfl_xor_sync(0xffffffffu, s[r][0], off);
            s[r][1] += __shfl_xor_sync(0xffffffffu, s[r][1], off);
        }
    if (t4 == 0) {
        #pragma unroll
        for (int r = 0; r < 4; r++) {
            sred[(wn * 64 + C + g + r * 8) * 2 + 0] = s[r][0];
            sred[(wn * 64 + C + g + r * 8) * 2 + 1] = s[r][1];
        }
    }
    __syncthreads();

    float mu[4], rs[4];
    #pragma unroll
    for (int r = 0; r < 4; r++) {
        int row = C + g + r * 8;
        float S1 = sred[(0 * 64 + row) * 2] + sred[(1 * 64 + row) * 2]
                 + sred[(2 * 64 + row) * 2] + sred[(3 * 64 + row) * 2];
        float S2 = sred[(0 * 64 + row) * 2 + 1] + sred[(1 * 64 + row) * 2 + 1]
                 + sred[(2 * 64 + row) * 2 + 1] + sred[(3 * 64 + row) * 2 + 1];
        mu[r] = S1 * (1.0f / 128.0f);
        float var = S2 * (1.0f / 128.0f) - mu[r] * mu[r];
        rs[r] = rsqrtf(var + 1e-5f);
    }

    #pragma unroll
    for (int nt = 0; nt < 4; nt++) {
        int c = wn * 32 + nt * 8 + 2 * t4;
        float2 gv = *(const float2*)&gma[c];
        float2 bv = *(const float2*)&bta[c];
        #pragma unroll
        for (int r = 0; r < 4; r++) {
            int gn = node0 + C + g + r * 8;
            if (gn >= NN) continue;
            float v0, v1;
            if (r == 0)      { v0 = acc0[nt][0]; v1 = acc0[nt][1]; }
            else if (r == 1) { v0 = acc0[nt][2]; v1 = acc0[nt][3]; }
            else if (r == 2) { v0 = acc1[nt][0]; v1 = acc1[nt][1]; }
            else             { v0 = acc1[nt][2]; v1 = acc1[nt][3]; }
            float2 res = *(const float2*)&xin[(size_t)gn * D + c];
            float o0 = gelu_exact((v0 - mu[r]) * rs[r] * gv.x + bv.x) + res.x;
            float o1 = gelu_exact((v1 - mu[r]) * rs[r] * gv.y + bv.y) + res.y;
            *(float2*)&xout[(size_t)gn * D + c] = make_float2(o0, o1);
        }
    }
}

// ---- sage_pq (layer 2 + pq GEMM fused): double-buffered phase 1 (buffer 1
//      carved from the Xr region, dead until the epilogue), then
//      [p|q] = x2 @ [Wl3|Wr3] from resident Xr. x2 never touches global.

__global__ __launch_bounds__(256, 2) void sage_pq(
    const float* __restrict__ xin,
    const float* __restrict__ Wl, const float* __restrict__ bl,
    const float* __restrict__ Wr,
    const float* __restrict__ gma, const float* __restrict__ bta,
    const float* __restrict__ Wl3, const float* __restrict__ Wr3)
{
    extern __shared__ uint32_t dsm[];
    uint32_t* buf0 = dsm;                          // 6784 u32
    float*    sred = (float*)(dsm + BUFU);         //  512 u32
    uint32_t* Xr   = dsm + BUFU + 512;             // 8448 u32 (buf1 = first 6784)
    uint32_t* buf1 = Xr;

    const int tid = threadIdx.x;
    const int node0 = blockIdx.x * 64;
    const int warp = tid >> 5, lane = tid & 31;
    const int wm = warp & 1, wn = warp >> 1;
    const int g = lane >> 2, t4 = lane & 3;

    const int an0 = tid >> 3, an1 = (tid + 256) >> 3, af = tid & 7;
    const int koff = (af >> 1) * 8 + (af & 1);
    const float4 f4z = make_float4(0.f, 0.f, 0.f, 0.f);

    auto ldA = [&](int kc, float4& r0, float4& r1) {
        const float4* Asrc = (kc < 4) ? (const float4*)g_agg : (const float4*)xin;
        int kb = (kc & 3) * 8;
        int gn0 = node0 + an0, gn1 = node0 + an1;
        r0 = (gn0 < NN) ? __ldg(&Asrc[(size_t)gn0 * 32 + kb + af]) : f4z;
        r1 = (gn1 < NN) ? __ldg(&Asrc[(size_t)gn1 * 32 + kb + af]) : f4z;
    };
    auto stA = [&](uint32_t* B, float4 r0, float4 r1) {
        B[an0 * 40 + koff + 0] = f2tf32(r0.x);
        B[an0 * 40 + koff + 2] = f2tf32(r0.y);
        B[an0 * 40 + koff + 4] = f2tf32(r0.z);
        B[an0 * 40 + koff + 6] = f2tf32(r0.w);
        B[an1 * 40 + koff + 0] = f2tf32(r1.x);
        B[an1 * 40 + koff + 2] = f2tf32(r1.y);
        B[an1 * 40 + koff + 4] = f2tf32(r1.z);
        B[an1 * 40 + koff + 6] = f2tf32(r1.w);
    };
    auto ldW = [&](int kc, float4* w) {
        const float4* Wsrc = (kc < 4) ? (const float4*)Wl : (const float4*)Wr;
        int kr0 = (kc & 3) * 32;
        int p0 = 2 * warp, p1 = 2 * warp + 1;
        int k0 = (p0 >> 2) * 8 + (p0 & 3);
        int k1 = (p1 >> 2) * 8 + (p1 & 3);
        w[0] = __ldg(&Wsrc[(size_t)(kr0 + k0) * 32 + lane]);
        w[1] = __ldg(&Wsrc[(size_t)(kr0 + k0 + 4) * 32 + lane]);
        w[2] = __ldg(&Wsrc[(size_t)(kr0 + k1) * 32 + lane]);
        w[3] = __ldg(&Wsrc[(size_t)(kr0 + k1 + 4) * 32 + lane]);
    };
    auto ldW3 = [&](int kc, float4* w) {
        int kr0 = kc * 32;
        int p0 = 2 * warp, p1 = 2 * warp + 1;
        int k0 = (p0 >> 2) * 8 + (p0 & 3);
        int k1 = (p1 >> 2) * 8 + (p1 & 3);
        const float4* Wsrc = (lane < 16) ? (const float4*)Wl3 : (const float4*)Wr3;
        int cl = lane & 15;
        w[0] = __ldg(&Wsrc[(size_t)(kr0 + k0) * 16 + cl]);
        w[1] = __ldg(&Wsrc[(size_t)(kr0 + k0 + 4) * 16 + cl]);
        w[2] = __ldg(&Wsrc[(size_t)(kr0 + k1) * 16 + cl]);
        w[3] = __ldg(&Wsrc[(size_t)(kr0 + k1 + 4) * 16 + cl]);
    };
    auto stW = [&](uint32_t* B, const float4* w) {
        uint4* W4 = (uint4*)(B + 2560);
        #pragma unroll
        for (int q = 0; q < 2; q++) {
            int p = 2 * warp + q;
            float4 lo = w[2 * q], hi = w[2 * q + 1];
            W4[p * 66 + 2 * lane]     = make_uint4(f2tf32(lo.x), f2tf32(hi.x),
                                                   f2tf32(lo.y), f2tf32(hi.y));
            W4[p * 66 + 2 * lane + 1] = make_uint4(f2tf32(lo.z), f2tf32(hi.z),
                                                   f2tf32(lo.w), f2tf32(hi.w));
        }
    };

    float acc0[4][4], acc1[4][4];
    #pragma unroll
    for (int i = 0; i < 4; i++)
        #pragma unroll
        for (int j = 0; j < 4; j++) { acc0[i][j] = 0.f; acc1[i][j] = 0.f; }

    {
        float4 a0, a1, w0[4];
        ldA(0, a0, a1); ldW(0, w0);
        stA(buf0, a0, a1); stW(buf0, w0);
    }
    __syncthreads();

    const int C = wm * 32;
    for (int kc = 0; kc < 8; kc++) {
        float4 na0, na1, nw[4];
        if (kc < 7) { ldA(kc + 1, na0, na1); ldW(kc + 1, nw); }
        uint32_t* B = (kc & 1) ? buf1 : buf0;
        const uint2* Apk = (const uint2*)B;
        const uint2* Wpk = (const uint2*)(B + 2560);
        #pragma unroll
        for (int kk = 0; kk < 4; kk++) {
            int pbase = kk * 4 + t4;
            uint2 qa0 = Apk[(C + g)      * ASTR2 + pbase];
            uint2 qa1 = Apk[(C + g + 8)  * ASTR2 + pbase];
            uint2 qa2 = Apk[(C + g + 16) * ASTR2 + pbase];
            uint2 qa3 = Apk[(C + g + 24) * ASTR2 + pbase];
            #pragma unroll
            for (int nt = 0; nt < 4; nt++) {
                uint2 qb = Wpk[pbase * WSTR2 + wn * 32 + nt * 8 + g];
                mma_tf32(acc0[nt], qa0.x, qa1.x, qa0.y, qa1.y, qb.x, qb.y);
                mma_tf32(acc1[nt], qa2.x, qa3.x, qa2.y, qa3.y, qb.x, qb.y);
            }
        }
        if (kc < 7) {
            uint32_t* Bn = (kc & 1) ? buf0 : buf1;
            stA(Bn, na0, na1); stW(Bn, nw);
            __syncthreads();
        }
    }
    __syncthreads();   // all warps done reading buf1 (Xr region) before epilogue writes Xr

    // ---- epilogue: + bl -> LN -> GELU -> + residual -> Xr (tf32, smem only) ----
    float s[4][2];
    #pragma unroll
    for (int r = 0; r < 4; r++) { s[r][0] = 0.f; s[r][1] = 0.f; }
    #pragma unroll
    for (int nt = 0; nt < 4; nt++) {
        int c = wn * 32 + nt * 8 + 2 * t4;
        float2 blv = *(const float2*)&bl[c];
        acc0[nt][0] += blv.x; acc0[nt][1] += blv.y;
        acc0[nt][2] += blv.x; acc0[nt][3] += blv.y;
        acc1[nt][0] += blv.x; acc1[nt][1] += blv.y;
        acc1[nt][2] += blv.x; acc1[nt][3] += blv.y;
        s[0][0] += acc0[nt][0] + acc0[nt][1];
        s[0][1] += acc0[nt][0]*acc0[nt][0] + acc0[nt][1]*acc0[nt][1];
        s[1][0] += acc0[nt][2] + acc0[nt][3];
        s[1][1] += acc0[nt][2]*acc0[nt][2] + acc0[nt][3]*acc0[nt][3];
        s[2][0] += acc1[nt][0] + acc1[nt][1];
        s[2][1] += acc1[nt][0]*acc1[nt][0] + acc1[nt][1]*acc1[nt][1];
        s[3][0] += acc1[nt][2] + acc1[nt][3];
        s[3][1] += acc1[nt][2]*acc1[nt][2] + acc1[nt][3]*acc1[nt][3];
    }
    #pragma unroll
    for (int off = 1; off <= 2; off <<= 1)
        #pragma unroll
        for (int r = 0; r < 4; r++) {
            s[r][0] += __shfl_xor_sync(0xffffffffu, s[r][0], off);
            s[r][1] += __shfl_xor_sync(0xffffffffu, s[r][1], off);
        }
    if (t4 == 0) {
        #pragma unroll
        for (int r = 0; r < 4; r++) {
            sred[(wn * 64 + C + g + r * 8) * 2 + 0] = s[r][0];
            sred[(wn * 64 + C + g + r * 8) * 2 + 1] = s[r][1];
        }
    }
    __syncthreads();

    float mu[4], rs[4];
    #pragma unroll
    for (int r = 0; r < 4; r++) {
        int row = C + g + r * 8;
        float S1 = sred[(0 * 64 + row) * 2] + sred[(1 * 64 + row) * 2]
                 + sred[(2 * 64 + row) * 2] + sred[(3 * 64 + row) * 2];
        float S2 = sred[(0 * 64 + row) * 2 + 1] + sred[(1 * 64 + row) * 2 + 1]
                 + sred[(2 * 64 + row) * 2 + 1] + sred[(3 * 64 + row) * 2 + 1];
        mu[r] = S1 * (1.0f / 128.0f);
        float var = S2 * (1.0f / 128.0f) - mu[r] * mu[r];
        rs[r] = rsqrtf(var + 1e-5f);
    }

    #pragma unroll
    for (int nt = 0; nt < 4; nt++) {
        int c = wn * 32 + nt * 8 + 2 * t4;
        float2 gv = *(const float2*)&gma[c];
        float2 bv = *(const float2*)&bta[c];
        #pragma unroll
        for (int r = 0; r < 4; r++) {
            int row = C + g + r * 8;
            int gn = node0 + row;
            float v0, v1;
            if (r == 0)      { v0 = acc0[nt][0]; v1 = acc0[nt][1]; }
            else if (r == 1) { v0 = acc0[nt][2]; v1 = acc0[nt][3]; }
            else if (r == 2) { v0 = acc1[nt][0]; v1 = acc1[nt][1]; }
            else             { v0 = acc1[nt][2]; v1 = acc1[nt][3]; }
            float o0 = 0.f, o1 = 0.f;
            if (gn < NN) {
                float2 res = *(const float2*)&xin[(size_t)gn * D + c];
                o0 = gelu_exact((v0 - mu[r]) * rs[r] * gv.x + bv.x) + res.x;
                o1 = gelu_exact((v1 - mu[r]) * rs[r] * gv.y + bv.y) + res.y;
            }
            Xr[row * ARSTR + c]     = f2tf32(o0);
            Xr[row * ARSTR + c + 1] = f2tf32(o1);
        }
    }
    __syncthreads();   // Xr complete; buf0's W region free for reuse

    // ---- pq GEMM: [p|q] = x2 @ [Wl3|Wr3], K=128 from resident Xr ----
    #pragma unroll
    for (int i = 0; i < 4; i++)
        #pragma unroll
        for (int j = 0; j < 4; j++) { acc0[i][j] = 0.f; acc1[i][j] = 0.f; }

    {
        float4 w0[4];
        ldW3(0, w0);
        stW(buf0, w0);
    }
    __syncthreads();

    const uint2* WpkQ = (const uint2*)(buf0 + 2560);
    for (int kc = 0; kc < 4; kc++) {
        float4 nw[4];
        if (kc < 3) ldW3(kc + 1, nw);
        #pragma unroll
        for (int kk = 0; kk < 4; kk++) {
            int kb = kc * 32 + kk * 8 + t4;
            uint32_t a00 = Xr[(C + g)      * ARSTR + kb];
            uint32_t a10 = Xr[(C + g + 8)  * ARSTR + kb];
            uint32_t a20 = Xr[(C + g + 16) * ARSTR + kb];
            uint32_t a30 = Xr[(C + g + 24) * ARSTR + kb];
            uint32_t a01 = Xr[(C + g)      * ARSTR + kb + 4];
            uint32_t a11 = Xr[(C + g + 8)  * ARSTR + kb + 4];
            uint32_t a21 = Xr[(C + g + 16) * ARSTR + kb + 4];
            uint32_t a31 = Xr[(C + g + 24) * ARSTR + kb + 4];
            #pragma unroll
            for (int nt = 0; nt < 4; nt++) {
                uint2 qb = WpkQ[(kk * 4 + t4) * WSTR2 + wn * 32 + nt * 8 + g];
                mma_tf32(acc0[nt], a00, a10, a01, a11, qb.x, qb.y);
                mma_tf32(acc1[nt], a20, a30, a21, a31, qb.x, qb.y);
            }
        }
        __syncthreads();
        if (kc < 3) { stW(buf0, nw); __syncthreads(); }
    }

    #pragma unroll
    for (int nt = 0; nt < 4; nt++) {
        int c = wn * 32 + nt * 8 + 2 * t4;
        float* dstbuf = (c < 64) ? g_p : g_q;
        int cc = c & 63;
        #pragma unroll
        for (int r = 0; r < 4; r++) {
            int gn = node0 + C + g + r * 8;
            if (gn >= NN) continue;
            float v0, v1;
            if (r == 0)      { v0 = acc0[nt][0]; v1 = acc0[nt][1]; }
            else if (r == 1) { v0 = acc0[nt][2]; v1 = acc0[nt][3]; }
            else if (r == 2) { v0 = acc1[nt][0]; v1 = acc1[nt][1]; }
            else             { v0 = acc1[nt][2]; v1 = acc1[nt][3]; }
            *(float2*)&dstbuf[(size_t)gn * DO + cc] = make_float2(v0, v1);
        }
    }
}

// ---- out_fused64: gather(p) + gelu(+q+bl3) -> LN(64) -> @Wc + bcls ----
// 64-node tile per block (8 warps x 8 nodes) so Wc staging is amortized.

__global__ __launch_bounds__(256) void out_fused64(
    const float* __restrict__ bl3,
    const float* __restrict__ gc, const float* __restrict__ bc,
    const float* __restrict__ Wc, const float* __restrict__ bcls,
    float* __restrict__ out)
{
    __shared__ float Wcs[DO * NC];   // 10240 B
    __shared__ float bcs[NC];
    __shared__ float Vs[64 * 66];    // 16896 B
    const int tid = threadIdx.x;
    const int node0 = blockIdx.x * 64;
    const int warp = tid >> 5, lane = tid & 31;

    for (int i = tid; i < DO * NC; i += 256)
        Wcs[i] = __ldg(&Wc[i]);
    if (tid < NC) bcs[tid] = __ldg(&bcls[tid]);

    float2 b3v = __ldg(&((const float2*)bl3)[lane]);
    float2 gcv = __ldg(&((const float2*)gc)[lane]);
    float2 bcv = __ldg(&((const float2*)bc)[lane]);
    const float2* p2 = (const float2*)g_p;

    for (int nn = 0; nn < 8; nn++) {
        int ln = warp * 8 + nn;
        int gn = node0 + ln;
        if (gn >= NN) break;
        int start = g_off[gn], deg = g_deg[gn];
        const int* es = g_esrc + start;
        float2 a0 = make_float2(0.f, 0.f), a1 = a0, a2 = a0, a3 = a0;
        int e = 0;
        for (; e + 4 <= deg; e += 4) {
            int s0 = __ldg(es + e),     s1 = __ldg(es + e + 1);
            int s2 = __ldg(es + e + 2), s3 = __ldg(es + e + 3);
            float2 v0 = __ldg(&p2[(size_t)s0 * 32 + lane]);
            float2 v1 = __ldg(&p2[(size_t)s1 * 32 + lane]);
            float2 v2 = __ldg(&p2[(size_t)s2 * 32 + lane]);
            float2 v3 = __ldg(&p2[(size_t)s3 * 32 + lane]);
            a0.x += v0.x; a0.y += v0.y;
            a1.x += v1.x; a1.y += v1.y;
            a2.x += v2.x; a2.y += v2.y;
            a3.x += v3.x; a3.y += v3.y;
        }
        for (; e < deg; e++) {
            int s0 = __ldg(es + e);
            float2 v0 = __ldg(&p2[(size_t)s0 * 32 + lane]);
            a0.x += v0.x; a0.y += v0.y;
        }
        float inv = 1.0f / fmaxf((float)deg, 1.0f);
        float agx = (a0.x + a1.x + a2.x + a3.x) * inv;
        float agy = (a0.y + a1.y + a2.y + a3.y) * inv;

        float2 q = __ldg(&((const float2*)g_q)[(size_t)gn * 32 + lane]);
        float u0 = gelu_exact(agx + q.x + b3v.x);
        float u1 = gelu_exact(agy + q.y + b3v.y);
        float s1 = u0 + u1, s2 = u0 * u0 + u1 * u1;
        #pragma unroll
        for (int off = 16; off; off >>= 1) {
            s1 += __shfl_xor_sync(0xffffffffu, s1, off);
            s2 += __shfl_xor_sync(0xffffffffu, s2, off);
        }
        float mu = s1 * (1.0f / 64.0f);
        float var = s2 * (1.0f / 64.0f) - mu * mu;
        float rstd = rsqrtf(var + 1e-5f);
        Vs[ln * 66 + 2 * lane]     = (u0 - mu) * rstd * gcv.x + bcv.x;
        Vs[ln * 66 + 2 * lane + 1] = (u1 - mu) * rstd * gcv.y + bcv.y;
    }
    __syncthreads();

    int n = tid >> 2, cg = (tid & 3) * 10;
    int gn = node0 + n;
    if (gn >= NN) return;
    float o[10];
    #pragma unroll
    for (int j = 0; j < 10; j++) o[j] = bcs[cg + j];
    #pragma unroll 8
    for (int k = 0; k < DO; k++) {
        float vv = Vs[n * 66 + k];
        #pragma unroll
        for (int j = 0; j < 10; j++)
            o[j] += vv * Wcs[k * NC + cg + j];
    }
    #pragma unroll
    for (int j = 0; j < 10; j++)
        out[(size_t)gn * NC + cg + j] = o[j];
}

// ---------------- launcher ----------------

extern "C" void kernel_launch(void* const* d_in, const int* in_sizes, int n_in,
                              void* d_out, int out_size)
{
    const float* x    = (const float*)d_in[0];
    const int*   ei   = (const int*)d_in[1];
    const float* Wl1  = (const float*)d_in[2];
    const float* bl1  = (const float*)d_in[3];
    const float* Wr1  = (const float*)d_in[4];
    const float* g1   = (const float*)d_in[5];
    const float* b1   = (const float*)d_in[6];
    const float* Wl2  = (const float*)d_in[7];
    const float* bl2  = (const float*)d_in[8];
    const float* Wr2  = (const float*)d_in[9];
    const float* g2   = (const float*)d_in[10];
    const float* b2   = (const float*)d_in[11];
    const float* Wl3  = (const float*)d_in[12];
    const float* bl3  = (const float*)d_in[13];
    const float* Wr3  = (const float*)d_in[14];
    const float* gc   = (const float*)d_in[15];
    const float* bc   = (const float*)d_in[16];
    const float* Wc   = (const float*)d_in[17];
    const float* bcls = (const float*)d_in[18];
    const int* src = ei;
    const int* dst = ei + NE;
    float* out = (float*)d_out;

    void *p_x1 = nullptr, *p_deg = nullptr;
    cudaGetSymbolAddress(&p_x1, g_x1);
    cudaGetSymbolAddress(&p_deg, g_deg);

    const int smem_tc2 = (2 * BUFU + 512) * 4;            // 56320 B
    const int smem_pq  = (BUFU + 512 + 8448) * 4;         // 62976 B
    cudaFuncSetAttribute(sage_tc2, cudaFuncAttributeMaxDynamicSharedMemorySize, smem_tc2);
    cudaFuncSetAttribute(sage_pq, cudaFuncAttributeMaxDynamicSharedMemorySize, smem_pq);

    const int nbn = (NN + 63) / 64;
    const int nbe = (NE + 255) / 256;
    const int nbw = ((NN * 32) + 255) / 256;   // one warp per node

    // CSR build
    cudaMemsetAsync(p_deg, 0, (size_t)NN * sizeof(int));
    count_deg<<<nbe, 256>>>(dst);
    scan_local<<<SCAN_B, SCAN_T>>>();
    scan_add2<<<(NN + 255) / 256, 128>>>();
    fill_edges<<<nbe, 256>>>(src, dst);

    // Layer 1
    gather128<<<nbw, 256>>>(x);
    sage_tc2<<<nbn, 256, smem_tc2>>>(x, Wl1, bl1, Wr1, g1, b1, (float*)p_x1);

    // Layer 2 + pq GEMM fused (x2 never hits global memory)
    gather128<<<nbw, 256>>>((const float*)p_x1);
    sage_pq<<<nbn, 256, smem_pq>>>((const float*)p_x1, Wl2, bl2, Wr2, g2, b2, Wl3, Wr3);

    // Layer 3 tail: fused gather(p) + epilogue + classifier
    out_fused64<<<nbn, 256>>>(bl3, gc, bc, Wc, bcls, out);
}

// round 16
// speedup vs baseline: 1.0294x; 1.0233x over previous
#include <cuda_runtime.h>
#include <cuda_fp16.h>
#include <math.h>
#include <stdint.h>

#define NN 50000
#define NE 800000
#define D  128
#define DO 64
#define NC 40
#define SCAN_T 512
#define SCAN_B ((NN + SCAN_T - 1) / SCAN_T)   // 98

#define ASTR2 20   // uint2 stride per node (paired A layout)
#define WSTR2 132  // uint2 stride per pair-row (paired W layout)
#define ARSTR 132  // uint32 stride per node (resident x2 tile)
#define BUFU  6784 // u32 per operand buffer: A(2560) + W(4224)

// Scratch (device globals: no allocation allowed)
__device__ float  g_agg[(size_t)NN * D];
__device__ float  g_x1[(size_t)NN * D];
__device__ __half g_xh[(size_t)NN * D];    // fp16 copy of input x (layer-1 gather)
__device__ __half g_x1h[(size_t)NN * D];   // fp16 copy of x1 (layer-2 gather)
__device__ float  g_p[(size_t)NN * DO];
__device__ float  g_q[(size_t)NN * DO];
__device__ int    g_deg[NN];
__device__ int    g_off[NN];
__device__ int    g_off2[NN];
__device__ int    g_bsum[SCAN_B];
__device__ int    g_esrc[NE];

__device__ __forceinline__ float gelu_exact(float v) {
    return 0.5f * v * (1.0f + erff(v * 0.70710678118654752f));
}

__device__ __forceinline__ uint32_t f2tf32(float f) {
    uint32_t r;
    asm("cvt.rna.tf32.f32 %0, %1;" : "=r"(r) : "f"(f));
    return r;
}

__device__ __forceinline__ void mma_tf32(float* d,
    uint32_t a0, uint32_t a1, uint32_t a2, uint32_t a3,
    uint32_t b0, uint32_t b1)
{
    asm volatile(
        "mma.sync.aligned.m16n8k8.row.col.f32.tf32.tf32.f32 "
        "{%0,%1,%2,%3}, {%4,%5,%6,%7}, {%8,%9}, {%0,%1,%2,%3};"
        : "+f"(d[0]), "+f"(d[1]), "+f"(d[2]), "+f"(d[3])
        : "r"(a0), "r"(a1), "r"(a2), "r"(a3), "r"(b0), "r"(b1));
}

// ---------------- CSR build ----------------

__global__ void count_deg(const int* __restrict__ dst) {
    int e = blockIdx.x * blockDim.x + threadIdx.x;
    if (e < NE) atomicAdd(&g_deg[dst[e]], 1);
}

__global__ void scan_local() {
    __shared__ int s[SCAN_T];
    int t = threadIdx.x;
    int i = blockIdx.x * SCAN_T + t;
    int v = (i < NN) ? g_deg[i] : 0;
    s[t] = v;
    __syncthreads();
    #pragma unroll
    for (int off = 1; off < SCAN_T; off <<= 1) {
        int a = (t >= off) ? s[t - off] : 0;
        __syncthreads();
        s[t] += a;
        __syncthreads();
    }
    if (i < NN) g_off[i] = s[t] - v;
    if (t == SCAN_T - 1) g_bsum[blockIdx.x] = s[t];
}

__global__ void scan_add2() {   // <<<(NN+255)/256, 128>>>, 2 elems/thread
    __shared__ int s[128];
    int t = threadIdx.x;
    int v = (t < SCAN_B) ? g_bsum[t] : 0;
    s[t] = v;
    __syncthreads();
    #pragma unroll
    for (int off = 1; off < 128; off <<= 1) {
        int a = (t >= off) ? s[t - off] : 0;
        __syncthreads();
        s[t] += a;
        __syncthreads();
    }
    int inc = s[t];
    __syncthreads();
    s[t] = inc - v;                               // exclusive
    __syncthreads();
    int i0 = blockIdx.x * 256 + t;
    int i1 = i0 + 128;
    if (i0 < NN) { int o = g_off[i0] + s[i0 / SCAN_T]; g_off[i0] = o; g_off2[i0] = o; }
    if (i1 < NN) { int o = g_off[i1] + s[i1 / SCAN_T]; g_off[i1] = o; g_off2[i1] = o; }
}

__global__ void fill_edges(const int* __restrict__ src, const int* __restrict__ dst) {
    int e = blockIdx.x * blockDim.x + threadIdx.x;
    if (e >= NE) return;
    int d = dst[e];
    int pos = atomicAdd(&g_off2[d], 1);
    g_esrc[pos] = src[e];
}

// ---------------- fp32 -> fp16 conversion (input x) ----------------

__global__ void cvt_half(const float* __restrict__ x) {
    int i = blockIdx.x * blockDim.x + threadIdx.x;
    if (i < NN * D / 2) {
        float2 v = ((const float2*)x)[i];
        ((half2*)g_xh)[i] = __float22half2_rn(v);
    }
}

// ------- gather mean-aggregation over fp16 rows (half the L2 traffic) -------
// One warp per node; lane holds dims [4*lane..4*lane+3] (one uint2 = 4 halves).

__global__ __launch_bounds__(256) void gather128h(const __half* __restrict__ xh) {
    int gw = (blockIdx.x * blockDim.x + threadIdx.x) >> 5;
    int lane = threadIdx.x & 31;
    if (gw >= NN) return;
    int start = g_off[gw], deg = g_deg[gw];
    const int* es = g_esrc + start;
    const uint2* x8 = (const uint2*)xh;   // 32 uint2 per node row
    float4 a0 = make_float4(0.f,0.f,0.f,0.f), a1 = a0, a2 = a0, a3 = a0;
    int e = 0;
    for (; e + 4 <= deg; e += 4) {
        int s0 = __ldg(es + e),     s1 = __ldg(es + e + 1);
        int s2 = __ldg(es + e + 2), s3 = __ldg(es + e + 3);
        uint2 u0 = __ldg(&x8[(size_t)s0 * 32 + lane]);
        uint2 u1 = __ldg(&x8[(size_t)s1 * 32 + lane]);
        uint2 u2 = __ldg(&x8[(size_t)s2 * 32 + lane]);
        uint2 u3 = __ldg(&x8[(size_t)s3 * 32 + lane]);
        float2 f;
        f = __half22float2(*(half2*)&u0.x); a0.x += f.x; a0.y += f.y;
        f = __half22float2(*(half2*)&u0.y); a0.z += f.x; a0.w += f.y;
        f = __half22float2(*(half2*)&u1.x); a1.x += f.x; a1.y += f.y;
        f = __half22float2(*(half2*)&u1.y); a1.z += f.x; a1.w += f.y;
        f = __half22float2(*(half2*)&u2.x); a2.x += f.x; a2.y += f.y;
        f = __half22float2(*(half2*)&u2.y); a2.z += f.x; a2.w += f.y;
        f = __half22float2(*(half2*)&u3.x); a3.x += f.x; a3.y += f.y;
        f = __half22float2(*(half2*)&u3.y); a3.z += f.x; a3.w += f.y;
    }
    for (; e < deg; e++) {
        int s0 = __ldg(es + e);
        uint2 u0 = __ldg(&x8[(size_t)s0 * 32 + lane]);
        float2 f;
        f = __half22float2(*(half2*)&u0.x); a0.x += f.x; a0.y += f.y;
        f = __half22float2(*(half2*)&u0.y); a0.z += f.x; a0.w += f.y;
    }
    float inv = 1.0f / fmaxf((float)deg, 1.0f);
    float4 r;
    r.x = (a0.x + a1.x + a2.x + a3.x) * inv;
    r.y = (a0.y + a1.y + a2.y + a3.y) * inv;
    r.z = (a0.z + a1.z + a2.z + a3.z) * inv;
    r.w = (a0.w + a1.w + a2.w + a3.w) * inv;
    ((float4*)g_agg)[(size_t)gw * 32 + lane] = r;
}

// ---- SAGE block (layer 1): tf32 mma, double-buffered operand staging ----
// Also emits x1 as fp16 (g_x1h) for the layer-2 gather.

__global__ __launch_bounds__(256, 2) void sage_tc2(
    const float* __restrict__ xin,
    const float* __restrict__ Wl, const float* __restrict__ bl,
    const float* __restrict__ Wr,
    const float* __restrict__ gma, const float* __restrict__ bta,
    float* __restrict__ xout)
{
    extern __shared__ uint32_t dsm[];
    uint32_t* buf0 = dsm;
    uint32_t* buf1 = dsm + BUFU;
    float*    sred = (float*)(dsm + 2 * BUFU);

    const int tid = threadIdx.x;
    const int node0 = blockIdx.x * 64;
    const int warp = tid >> 5, lane = tid & 31;
    const int wm = warp & 1, wn = warp >> 1;
    const int g = lane >> 2, t4 = lane & 3;

    const int an0 = tid >> 3, an1 = (tid + 256) >> 3, af = tid & 7;
    const int koff = (af >> 1) * 8 + (af & 1);
    const float4 f4z = make_float4(0.f, 0.f, 0.f, 0.f);

    auto ldA = [&](int kc, float4& r0, float4& r1) {
        const float4* Asrc = (kc < 4) ? (const float4*)g_agg : (const float4*)xin;
        int kb = (kc & 3) * 8;
        int gn0 = node0 + an0, gn1 = node0 + an1;
        r0 = (gn0 < NN) ? __ldg(&Asrc[(size_t)gn0 * 32 + kb + af]) : f4z;
        r1 = (gn1 < NN) ? __ldg(&Asrc[(size_t)gn1 * 32 + kb + af]) : f4z;
    };
    auto stA = [&](uint32_t* B, float4 r0, float4 r1) {
        B[an0 * 40 + koff + 0] = f2tf32(r0.x);
        B[an0 * 40 + koff + 2] = f2tf32(r0.y);
        B[an0 * 40 + koff + 4] = f2tf32(r0.z);
        B[an0 * 40 + koff + 6] = f2tf32(r0.w);
        B[an1 * 40 + koff + 0] = f2tf32(r1.x);
        B[an1 * 40 + koff + 2] = f2tf32(r1.y);
        B[an1 * 40 + koff + 4] = f2tf32(r1.z);
        B[an1 * 40 + koff + 6] = f2tf32(r1.w);
    };
    auto ldW = [&](int kc, float4* w) {
        const float4* Wsrc = (kc < 4) ? (const float4*)Wl : (const float4*)Wr;
        int kr0 = (kc & 3) * 32;
        int p0 = 2 * warp, p1 = 2 * warp + 1;
        int k0 = (p0 >> 2) * 8 + (p0 & 3);
        int k1 = (p1 >> 2) * 8 + (p1 & 3);
        w[0] = __ldg(&Wsrc[(size_t)(kr0 + k0) * 32 + lane]);
        w[1] = __ldg(&Wsrc[(size_t)(kr0 + k0 + 4) * 32 + lane]);
        w[2] = __ldg(&Wsrc[(size_t)(kr0 + k1) * 32 + lane]);
        w[3] = __ldg(&Wsrc[(size_t)(kr0 + k1 + 4) * 32 + lane]);
    };
    auto stW = [&](uint32_t* B, const float4* w) {
        uint4* W4 = (uint4*)(B + 2560);
        #pragma unroll
        for (int q = 0; q < 2; q++) {
            int p = 2 * warp + q;
            float4 lo = w[2 * q], hi = w[2 * q + 1];
            W4[p * 66 + 2 * lane]     = make_uint4(f2tf32(lo.x), f2tf32(hi.x),
                                                   f2tf32(lo.y), f2tf32(hi.y));
            W4[p * 66 + 2 * lane + 1] = make_uint4(f2tf32(lo.z), f2tf32(hi.z),
                                                   f2tf32(lo.w), f2tf32(hi.w));
        }
    };

    float acc0[4][4], acc1[4][4];
    #pragma unroll
    for (int i = 0; i < 4; i++)
        #pragma unroll
        for (int j = 0; j < 4; j++) { acc0[i][j] = 0.f; acc1[i][j] = 0.f; }

    {
        float4 a0, a1, w0[4];
        ldA(0, a0, a1); ldW(0, w0);
        stA(buf0, a0, a1); stW(buf0, w0);
    }
    __syncthreads();

    const int C = wm * 32;
    for (int kc = 0; kc < 8; kc++) {
        float4 na0, na1, nw[4];
        if (kc < 7) { ldA(kc + 1, na0, na1); ldW(kc + 1, nw); }
        uint32_t* B = (kc & 1) ? buf1 : buf0;
        const uint2* Apk = (const uint2*)B;
        const uint2* Wpk = (const uint2*)(B + 2560);
        #pragma unroll
        for (int kk = 0; kk < 4; kk++) {
            int pbase = kk * 4 + t4;
            uint2 qa0 = Apk[(C + g)      * ASTR2 + pbase];
            uint2 qa1 = Apk[(C + g + 8)  * ASTR2 + pbase];
            uint2 qa2 = Apk[(C + g + 16) * ASTR2 + pbase];
            uint2 qa3 = Apk[(C + g + 24) * ASTR2 + pbase];
            #pragma unroll
            for (int nt = 0; nt < 4; nt++) {
                uint2 qb = Wpk[pbase * WSTR2 + wn * 32 + nt * 8 + g];
                mma_tf32(acc0[nt], qa0.x, qa1.x, qa0.y, qa1.y, qb.x, qb.y);
                mma_tf32(acc1[nt], qa2.x, qa3.x, qa2.y, qa3.y, qb.x, qb.y);
            }
        }
        if (kc < 7) {
            uint32_t* Bn = (kc & 1) ? buf0 : buf1;
            stA(Bn, na0, na1); stW(Bn, nw);
            __syncthreads();
        }
    }

    // ---- epilogue: + bl -> LN (128 cols) -> GELU -> + residual ----
    float s[4][2];
    #pragma unroll
    for (int r = 0; r < 4; r++) { s[r][0] = 0.f; s[r][1] = 0.f; }
    #pragma unroll
    for (int nt = 0; nt < 4; nt++) {
        int c = wn * 32 + nt * 8 + 2 * t4;
        float2 blv = *(const float2*)&bl[c];
        acc0[nt][0] += blv.x; acc0[nt][1] += blv.y;
        acc0[nt][2] += blv.x; acc0[nt][3] += blv.y;
        acc1[nt][0] += blv.x; acc1[nt][1] += blv.y;
        acc1[nt][2] += blv.x; acc1[nt][3] += blv.y;
        s[0][0] += acc0[nt][0] + acc0[nt][1];
        s[0][1] += acc0[nt][0]*acc0[nt][0] + acc0[nt][1]*acc0[nt][1];
        s[1][0] += acc0[nt][2] + acc0[nt][3];
        s[1][1] += acc0[nt][2]*acc0[nt][2] + acc0[nt][3]*acc0[nt][3];
        s[2][0] += acc1[nt][0] + acc1[nt][1];
        s[2][1] += acc1[nt][0]*acc1[nt][0] + acc1[nt][1]*acc1[nt][1];
        s[3][0] += acc1[nt][2] + acc1[nt][3];
        s[3][1] += acc1[nt][2]*acc1[nt][2] + acc1[nt][3]*acc1[nt][3];
    }
    #pragma unroll
    for (int off = 1; off <= 2; off <<= 1)
        #pragma unroll
        for (int r = 0; r < 4; r++) {
            s[r][0] += __shfl_xor_sync(0xffffffffu, s[r][0], off);
            s[r][1] += __shfl_xor_sync(0xffffffffu, s[r][1], off);
        }
    if (t4 == 0) {
        #pragma unroll
        for (int r = 0; r < 4; r++) {
            sred[(wn * 64 + C + g + r * 8) * 2 + 0] = s[r][0];
            sred[(wn * 64 + C + g + r * 8) * 2 + 1] = s[r][1];
        }
    }
    __syncthreads();

    float mu[4], rs[4];
    #pragma unroll
    for (int r = 0; r < 4; r++) {
        int row = C + g + r * 8;
        float S1 = sred[(0 * 64 + row) * 2] + sred[(1 * 64 + row) * 2]
                 + sred[(2 * 64 + row) * 2] + sred[(3 * 64 + row) * 2];
        float S2 = sred[(0 * 64 + row) * 2 + 1] + sred[(1 * 64 + row) * 2 + 1]
                 + sred[(2 * 64 + row) * 2 + 1] + sred[(3 * 64 + row) * 2 + 1];
        mu[r] = S1 * (1.0f / 128.0f);
        float var = S2 * (1.0f / 128.0f) - mu[r] * mu[r];
        rs[r] = rsqrtf(var + 1e-5f);
    }

    #pragma unroll
    for (int nt = 0; nt < 4; nt++) {
        int c = wn * 32 + nt * 8 + 2 * t4;
        float2 gv = *(const float2*)&gma[c];
        float2 bv = *(const float2*)&bta[c];
        #pragma unroll
        for (int r = 0; r < 4; r++) {
            int gn = node0 + C + g + r * 8;
            if (gn >= NN) continue;
            float v0, v1;
            if (r == 0)      { v0 = acc0[nt][0]; v1 = acc0[nt][1]; }
            else if (r == 1) { v0 = acc0[nt][2]; v1 = acc0[nt][3]; }
            else if (r == 2) { v0 = acc1[nt][0]; v1 = acc1[nt][1]; }
            else             { v0 = acc1[nt][2]; v1 = acc1[nt][3]; }
            float2 res = *(const float2*)&xin[(size_t)gn * D + c];
            float o0 = gelu_exact((v0 - mu[r]) * rs[r] * gv.x + bv.x) + res.x;
            float o1 = gelu_exact((v1 - mu[r]) * rs[r] * gv.y + bv.y) + res.y;
            *(float2*)&xout[(size_t)gn * D + c] = make_float2(o0, o1);
            ((half2*)g_x1h)[(size_t)gn * 64 + (c >> 1)] =
                __float22half2_rn(make_float2(o0, o1));
        }
    }
}

// ---- sage_pq (layer 2 + pq GEMM fused): double-buffered phase 1, then
//      [p|q] = x2 @ [Wl3|Wr3] from resident Xr. x2 never touches global.

__global__ __launch_bounds__(256, 2) void sage_pq(
    const float* __restrict__ xin,
    const float* __restrict__ Wl, const float* __restrict__ bl,
    const float* __restrict__ Wr,
    const float* __restrict__ gma, const float* __restrict__ bta,
    const float* __restrict__ Wl3, const float* __restrict__ Wr3)
{
    extern __shared__ uint32_t dsm[];
    uint32_t* buf0 = dsm;                          // 6784 u32
    float*    sred = (float*)(dsm + BUFU);         //  512 u32
    uint32_t* Xr   = dsm + BUFU + 512;             // 8448 u32 (buf1 = first 6784)
    uint32_t* buf1 = Xr;

    const int tid = threadIdx.x;
    const int node0 = blockIdx.x * 64;
    const int warp = tid >> 5, lane = tid & 31;
    const int wm = warp & 1, wn = warp >> 1;
    const int g = lane >> 2, t4 = lane & 3;

    const int an0 = tid >> 3, an1 = (tid + 256) >> 3, af = tid & 7;
    const int koff = (af >> 1) * 8 + (af & 1);
    const float4 f4z = make_float4(0.f, 0.f, 0.f, 0.f);

    auto ldA = [&](int kc, float4& r0, float4& r1) {
        const float4* Asrc = (kc < 4) ? (const float4*)g_agg : (const float4*)xin;
        int kb = (kc & 3) * 8;
        int gn0 = node0 + an0, gn1 = node0 + an1;
        r0 = (gn0 < NN) ? __ldg(&Asrc[(size_t)gn0 * 32 + kb + af]) : f4z;
        r1 = (gn1 < NN) ? __ldg(&Asrc[(size_t)gn1 * 32 + kb + af]) : f4z;
    };
    auto stA = [&](uint32_t* B, float4 r0, float4 r1) {
        B[an0 * 40 + koff + 0] = f2tf32(r0.x);
        B[an0 * 40 + koff + 2] = f2tf32(r0.y);
        B[an0 * 40 + koff + 4] = f2tf32(r0.z);
        B[an0 * 40 + koff + 6] = f2tf32(r0.w);
        B[an1 * 40 + koff + 0] = f2tf32(r1.x);
        B[an1 * 40 + koff + 2] = f2tf32(r1.y);
        B[an1 * 40 + koff + 4] = f2tf32(r1.z);
        B[an1 * 40 + koff + 6] = f2tf32(r1.w);
    };
    auto ldW = [&](int kc, float4* w) {
        const float4* Wsrc = (kc < 4) ? (const float4*)Wl : (const float4*)Wr;
        int kr0 = (kc & 3) * 32;
        int p0 = 2 * warp, p1 = 2 * warp + 1;
        int k0 = (p0 >> 2) * 8 + (p0 & 3);
        int k1 = (p1 >> 2) * 8 + (p1 & 3);
        w[0] = __ldg(&Wsrc[(size_t)(kr0 + k0) * 32 + lane]);
        w[1] = __ldg(&Wsrc[(size_t)(kr0 + k0 + 4) * 32 + lane]);
        w[2] = __ldg(&Wsrc[(size_t)(kr0 + k1) * 32 + lane]);
        w[3] = __ldg(&Wsrc[(size_t)(kr0 + k1 + 4) * 32 + lane]);
    };
    auto ldW3 = [&](int kc, float4* w) {
        int kr0 = kc * 32;
        int p0 = 2 * warp, p1 = 2 * warp + 1;
        int k0 = (p0 >> 2) * 8 + (p0 & 3);
        int k1 = (p1 >> 2) * 8 + (p1 & 3);
        const float4* Wsrc = (lane < 16) ? (const float4*)Wl3 : (const float4*)Wr3;
        int cl = lane & 15;
        w[0] = __ldg(&Wsrc[(size_t)(kr0 + k0) * 16 + cl]);
        w[1] = __ldg(&Wsrc[(size_t)(kr0 + k0 + 4) * 16 + cl]);
        w[2] = __ldg(&Wsrc[(size_t)(kr0 + k1) * 16 + cl]);
        w[3] = __ldg(&Wsrc[(size_t)(kr0 + k1 + 4) * 16 + cl]);
    };
    auto stW = [&](uint32_t* B, const float4* w) {
        uint4* W4 = (uint4*)(B + 2560);
        #pragma unroll
        for (int q = 0; q < 2; q++) {
            int p = 2 * warp + q;
            float4 lo = w[2 * q], hi = w[2 * q + 1];
            W4[p * 66 + 2 * lane]     = make_uint4(f2tf32(lo.x), f2tf32(hi.x),
                                                   f2tf32(lo.y), f2tf32(hi.y));
            W4[p * 66 + 2 * lane + 1] = make_uint4(f2tf32(lo.z), f2tf32(hi.z),
                                                   f2tf32(lo.w), f2tf32(hi.w));
        }
    };

    float acc0[4][4], acc1[4][4];
    #pragma unroll
    for (int i = 0; i < 4; i++)
        #pragma unroll
        for (int j = 0; j < 4; j++) { acc0[i][j] = 0.f; acc1[i][j] = 0.f; }

    {
        float4 a0, a1, w0[4];
        ldA(0, a0, a1); ldW(0, w0);
        stA(buf0, a0, a1); stW(buf0, w0);
    }
    __syncthreads();

    const int C = wm * 32;
    for (int kc = 0; kc < 8; kc++) {
        float4 na0, na1, nw[4];
        if (kc < 7) { ldA(kc + 1, na0, na1); ldW(kc + 1, nw); }
        uint32_t* B = (kc & 1) ? buf1 : buf0;
        const uint2* Apk = (const uint2*)B;
        const uint2* Wpk = (const uint2*)(B + 2560);
        #pragma unroll
        for (int kk = 0; kk < 4; kk++) {
            int pbase = kk * 4 + t4;
            uint2 qa0 = Apk[(C + g)      * ASTR2 + pbase];
            uint2 qa1 = Apk[(C + g + 8)  * ASTR2 + pbase];
            uint2 qa2 = Apk[(C + g + 16) * ASTR2 + pbase];
            uint2 qa3 = Apk[(C + g + 24) * ASTR2 + pbase];
            #pragma unroll
            for (int nt = 0; nt < 4; nt++) {
                uint2 qb = Wpk[pbase * WSTR2 + wn * 32 + nt * 8 + g];
                mma_tf32(acc0[nt], qa0.x, qa1.x, qa0.y, qa1.y, qb.x, qb.y);
                mma_tf32(acc1[nt], qa2.x, qa3.x, qa2.y, qa3.y, qb.x, qb.y);
            }
        }
        if (kc < 7) {
            uint32_t* Bn = (kc & 1) ? buf0 : buf1;
            stA(Bn, na0, na1); stW(Bn, nw);
            __syncthreads();
        }
    }
    __syncthreads();   // all warps done reading buf1 (Xr region) before epilogue writes Xr

    // ---- epilogue: + bl -> LN -> GELU -> + residual -> Xr (tf32, smem only) ----
    float s[4][2];
    #pragma unroll
    for (int r = 0; r < 4; r++) { s[r][0] = 0.f; s[r][1] = 0.f; }
    #pragma unroll
    for (int nt = 0; nt < 4; nt++) {
        int c = wn * 32 + nt * 8 + 2 * t4;
        float2 blv = *(const float2*)&bl[c];
        acc0[nt][0] += blv.x; acc0[nt][1] += blv.y;
        acc0[nt][2] += blv.x; acc0[nt][3] += blv.y;
        acc1[nt][0] += blv.x; acc1[nt][1] += blv.y;
        acc1[nt][2] += blv.x; acc1[nt][3] += blv.y;
        s[0][0] += acc0[nt][0] + acc0[nt][1];
        s[0][1] += acc0[nt][0]*acc0[nt][0] + acc0[nt][1]*acc0[nt][1];
        s[1][0] += acc0[nt][2] + acc0[nt][3];
        s[1][1] += acc0[nt][2]*acc0[nt][2] + acc0[nt][3]*acc0[nt][3];
        s[2][0] += acc1[nt][0] + acc1[nt][1];
        s[2][1] += acc1[nt][0]*acc1[nt][0] + acc1[nt][1]*acc1[nt][1];
        s[3][0] += acc1[nt][2] + acc1[nt][3];
        s[3][1] += acc1[nt][2]*acc1[nt][2] + acc1[nt][3]*acc1[nt][3];
    }
    #pragma unroll
    for (int off = 1; off <= 2; off <<= 1)
        #pragma unroll
        for (int r = 0; r < 4; r++) {
            s[r][0] += __shfl_xor_sync(0xffffffffu, s[r][0], off);
            s[r][1] += __shfl_xor_sync(0xffffffffu, s[r][1], off);
        }
    if (t4 == 0) {
        #pragma unroll
        for (int r = 0; r < 4; r++) {
            sred[(wn * 64 + C + g + r * 8) * 2 + 0] = s[r][0];
            sred[(wn * 64 + C + g + r * 8) * 2 + 1] = s[r][1];
        }
    }
    __syncthreads();

    float mu[4], rs[4];
    #pragma unroll
    for (int r = 0; r < 4; r++) {
        int row = C + g + r * 8;
        float S1 = sred[(0 * 64 + row) * 2] + sred[(1 * 64 + row) * 2]
                 + sred[(2 * 64 + row) * 2] + sred[(3 * 64 + row) * 2];
        float S2 = sred[(0 * 64 + row) * 2 + 1] + sred[(1 * 64 + row) * 2 + 1]
                 + sred[(2 * 64 + row) * 2 + 1] + sred[(3 * 64 + row) * 2 + 1];
        mu[r] = S1 * (1.0f / 128.0f);
        float var = S2 * (1.0f / 128.0f) - mu[r] * mu[r];
        rs[r] = rsqrtf(var + 1e-5f);
    }

    #pragma unroll
    for (int nt = 0; nt < 4; nt++) {
        int c = wn * 32 + nt * 8 + 2 * t4;
        float2 gv = *(const float2*)&gma[c];
        float2 bv = *(const float2*)&bta[c];
        #pragma unroll
        for (int r = 0; r < 4; r++) {
            int row = C + g + r * 8;
            int gn = node0 + row;
            float v0, v1;
            if (r == 0)      { v0 = acc0[nt][0]; v1 = acc0[nt][1]; }
            else if (r == 1) { v0 = acc0[nt][2]; v1 = acc0[nt][3]; }
            else if (r == 2) { v0 = acc1[nt][0]; v1 = acc1[nt][1]; }
            else             { v0 = acc1[nt][2]; v1 = acc1[nt][3]; }
            float o0 = 0.f, o1 = 0.f;
            if (gn < NN) {
                float2 res = *(const float2*)&xin[(size_t)gn * D + c];
                o0 = gelu_exact((v0 - mu[r]) * rs[r] * gv.x + bv.x) + res.x;
                o1 = gelu_exact((v1 - mu[r]) * rs[r] * gv.y + bv.y) + res.y;
            }
            Xr[row * ARSTR + c]     = f2tf32(o0);
            Xr[row * ARSTR + c + 1] = f2tf32(o1);
        }
    }
    __syncthreads();   // Xr complete; buf0's W region free for reuse

    // ---- pq GEMM: [p|q] = x2 @ [Wl3|Wr3], K=128 from resident Xr ----
    #pragma unroll
    for (int i = 0; i < 4; i++)
        #pragma unroll
        for (int j = 0; j < 4; j++) { acc0[i][j] = 0.f; acc1[i][j] = 0.f; }

    {
        float4 w0[4];
        ldW3(0, w0);
        stW(buf0, w0);
    }
    __syncthreads();

    const uint2* WpkQ = (const uint2*)(buf0 + 2560);
    for (int kc = 0; kc < 4; kc++) {
        float4 nw[4];
        if (kc < 3) ldW3(kc + 1, nw);
        #pragma unroll
        for (int kk = 0; kk < 4; kk++) {
            int kb = kc * 32 + kk * 8 + t4;
            uint32_t a00 = Xr[(C + g)      * ARSTR + kb];
            uint32_t a10 = Xr[(C + g + 8)  * ARSTR + kb];
            uint32_t a20 = Xr[(C + g + 16) * ARSTR + kb];
            uint32_t a30 = Xr[(C + g + 24) * ARSTR + kb];
            uint32_t a01 = Xr[(C + g)      * ARSTR + kb + 4];
            uint32_t a11 = Xr[(C + g + 8)  * ARSTR + kb + 4];
            uint32_t a21 = Xr[(C + g + 16) * ARSTR + kb + 4];
            uint32_t a31 = Xr[(C + g + 24) * ARSTR + kb + 4];
            #pragma unroll
            for (int nt = 0; nt < 4; nt++) {
                uint2 qb = WpkQ[(kk * 4 + t4) * WSTR2 + wn * 32 + nt * 8 + g];
                mma_tf32(acc0[nt], a00, a10, a01, a11, qb.x, qb.y);
                mma_tf32(acc1[nt], a20, a30, a21, a31, qb.x, qb.y);
            }
        }
        __syncthreads();
        if (kc < 3) { stW(buf0, nw); __syncthreads(); }
    }

    #pragma unroll
    for (int nt = 0; nt < 4; nt++) {
        int c = wn * 32 + nt * 8 + 2 * t4;
        float* dstbuf = (c < 64) ? g_p : g_q;
        int cc = c & 63;
        #pragma unroll
        for (int r = 0; r < 4; r++) {
            int gn = node0 + C + g + r * 8;
            if (gn >= NN) continue;
            float v0, v1;
            if (r == 0)      { v0 = acc0[nt][0]; v1 = acc0[nt][1]; }
            else if (r == 1) { v0 = acc0[nt][2]; v1 = acc0[nt][3]; }
            else if (r == 2) { v0 = acc1[nt][0]; v1 = acc1[nt][1]; }
            else             { v0 = acc1[nt][2]; v1 = acc1[nt][3]; }
            *(float2*)&dstbuf[(size_t)gn * DO + cc] = make_float2(v0, v1);
        }
    }
}

// ---- out_fused64: gather(p) + gelu(+q+bl3) -> LN(64) -> @Wc + bcls ----

__global__ __launch_bounds__(256) void out_fused64(
    const float* __restrict__ bl3,
    const float* __restrict__ gc, const float* __restrict__ bc,
    const float* __restrict__ Wc, const float* __restrict__ bcls,
    float* __restrict__ out)
{
    __shared__ float Wcs[DO * NC];
    __shared__ float bcs[NC];
    __shared__ float Vs[64 * 66];
    const int tid = threadIdx.x;
    const int node0 = blockIdx.x * 64;
    const int warp = tid >> 5, lane = tid & 31;

    for (int i = tid; i < DO * NC; i += 256)
        Wcs[i] = __ldg(&Wc[i]);
    if (tid < NC) bcs[tid] = __ldg(&bcls[tid]);

    float2 b3v = __ldg(&((const float2*)bl3)[lane]);
    float2 gcv = __ldg(&((const float2*)gc)[lane]);
    float2 bcv = __ldg(&((const float2*)bc)[lane]);
    const float2* p2 = (const float2*)g_p;

    for (int nn = 0; nn < 8; nn++) {
        int ln = warp * 8 + nn;
        int gn = node0 + ln;
        if (gn >= NN) break;
        int start = g_off[gn], deg = g_deg[gn];
        const int* es = g_esrc + start;
        float2 a0 = make_float2(0.f, 0.f), a1 = a0, a2 = a0, a3 = a0;
        int e = 0;
        for (; e + 4 <= deg; e += 4) {
            int s0 = __ldg(es + e),     s1 = __ldg(es + e + 1);
            int s2 = __ldg(es + e + 2), s3 = __ldg(es + e + 3);
            float2 v0 = __ldg(&p2[(size_t)s0 * 32 + lane]);
            float2 v1 = __ldg(&p2[(size_t)s1 * 32 + lane]);
            float2 v2 = __ldg(&p2[(size_t)s2 * 32 + lane]);
            float2 v3 = __ldg(&p2[(size_t)s3 * 32 + lane]);
            a0.x += v0.x; a0.y += v0.y;
            a1.x += v1.x; a1.y += v1.y;
            a2.x += v2.x; a2.y += v2.y;
            a3.x += v3.x; a3.y += v3.y;
        }
        for (; e < deg; e++) {
            int s0 = __ldg(es + e);
            float2 v0 = __ldg(&p2[(size_t)s0 * 32 + lane]);
            a0.x += v0.x; a0.y += v0.y;
        }
        float inv = 1.0f / fmaxf((float)deg, 1.0f);
        float agx = (a0.x + a1.x + a2.x + a3.x) * inv;
        float agy = (a0.y + a1.y + a2.y + a3.y) * inv;

        float2 q = __ldg(&((const float2*)g_q)[(size_t)gn * 32 + lane]);
        float u0 = gelu_exact(agx + q.x + b3v.x);
        float u1 = gelu_exact(agy + q.y + b3v.y);
        float s1 = u0 + u1, s2 = u0 * u0 + u1 * u1;
        #pragma unroll
        for (int off = 16; off; off >>= 1) {
            s1 += __shfl_xor_sync(0xffffffffu, s1, off);
            s2 += __shfl_xor_sync(0xffffffffu, s2, off);
        }
        float mu = s1 * (1.0f / 64.0f);
        float var = s2 * (1.0f / 64.0f) - mu * mu;
        float rstd = rsqrtf(var + 1e-5f);
        Vs[ln * 66 + 2 * lane]     = (u0 - mu) * rstd * gcv.x + bcv.x;
        Vs[ln * 66 + 2 * lane + 1] = (u1 - mu) * rstd * gcv.y + bcv.y;
    }
    __syncthreads();

    int n = tid >> 2, cg = (tid & 3) * 10;
    int gn = node0 + n;
    if (gn >= NN) return;
    float o[10];
    #pragma unroll
    for (int j = 0; j < 10; j++) o[j] = bcs[cg + j];
    #pragma unroll 8
    for (int k = 0; k < DO; k++) {
        float vv = Vs[n * 66 + k];
        #pragma unroll
        for (int j = 0; j < 10; j++)
            o[j] += vv * Wcs[k * NC + cg + j];
    }
    #pragma unroll
    for (int j = 0; j < 10; j++)
        out[(size_t)gn * NC + cg + j] = o[j];
}

// ---------------- launcher ----------------

extern "C" void kernel_launch(void* const* d_in, const int* in_sizes, int n_in,
                              void* d_out, int out_size)
{
    const float* x    = (const float*)d_in[0];
    const int*   ei   = (const int*)d_in[1];
    const float* Wl1  = (const float*)d_in[2];
    const float* bl1  = (const float*)d_in[3];
    const float* Wr1  = (const float*)d_in[4];
    const float* g1   = (const float*)d_in[5];
    const float* b1   = (const float*)d_in[6];
    const float* Wl2  = (const float*)d_in[7];
    const float* bl2  = (const float*)d_in[8];
    const float* Wr2  = (const float*)d_in[9];
    const float* g2   = (const float*)d_in[10];
    const float* b2   = (const float*)d_in[11];
    const float* Wl3  = (const float*)d_in[12];
    const float* bl3  = (const float*)d_in[13];
    const float* Wr3  = (const float*)d_in[14];
    const float* gc   = (const float*)d_in[15];
    const float* bc   = (const float*)d_in[16];
    const float* Wc   = (const float*)d_in[17];
    const float* bcls = (const float*)d_in[18];
    const int* src = ei;
    const int* dst = ei + NE;
    float* out = (float*)d_out;

    void *p_x1 = nullptr, *p_deg = nullptr, *p_xh = nullptr, *p_x1h = nullptr;
    cudaGetSymbolAddress(&p_x1, g_x1);
    cudaGetSymbolAddress(&p_deg, g_deg);
    cudaGetSymbolAddress(&p_xh, g_xh);
    cudaGetSymbolAddress(&p_x1h, g_x1h);

    const int smem_tc2 = (2 * BUFU + 512) * 4;            // 56320 B
    const int smem_pq  = (BUFU + 512 + 8448) * 4;         // 62976 B
    cudaFuncSetAttribute(sage_tc2, cudaFuncAttributeMaxDynamicSharedMemorySize, smem_tc2);
    cudaFuncSetAttribute(sage_pq, cudaFuncAttributeMaxDynamicSharedMemorySize, smem_pq);

    const int nbn = (NN + 63) / 64;
    const int nbe = (NE + 255) / 256;
    const int nbw = ((NN * 32) + 255) / 256;   // one warp per node

    // CSR build + fp16 conversion of x
    cudaMemsetAsync(p_deg, 0, (size_t)NN * sizeof(int));
    cvt_half<<<(NN * D / 2 + 255) / 256, 256>>>(x);
    count_deg<<<nbe, 256>>>(dst);
    scan_local<<<SCAN_B, SCAN_T>>>();
    scan_add2<<<(NN + 255) / 256, 128>>>();
    fill_edges<<<nbe, 256>>>(src, dst);

    // Layer 1 (fp16 gather payload)
    gather128h<<<nbw, 256>>>((const __half*)p_xh);
    sage_tc2<<<nbn, 256, smem_tc2>>>(x, Wl1, bl1, Wr1, g1, b1, (float*)p_x1);

    // Layer 2 + pq GEMM fused (fp16 gather payload; x2 never hits global)
    gather128h<<<nbw, 256>>>((const __half*)p_x1h);
    sage_pq<<<nbn, 256, smem_pq>>>((const float*)p_x1, Wl2, bl2, Wr2, g2, b2, Wl3, Wr3);

    // Layer 3 tail: fused gather(p) + epilogue + classifier
    out_fused64<<<nbn, 256>>>(bl3, gc, bc, Wc, bcls, out);
}

// round 17
// speedup vs baseline: 1.0503x; 1.0203x over previous
#include <cuda_runtime.h>
#include <cuda_fp16.h>
#include <math.h>
#include <stdint.h>

#define NN 50000
#define NE 800000
#define D  128
#define DO 64
#define NC 40
#define SCAN_T 512
#define SCAN_B ((NN + SCAN_T - 1) / SCAN_T)   // 98

#define ASTR2 20   // uint2 stride per node (paired A layout)
#define WSTR2 132  // uint2 stride per pair-row (paired W layout)
#define ARSTR 132  // uint32 stride per node (resident x2 tile)
#define BUFU  6784 // u32 per operand buffer: A(2560) + W(4224)

// Scratch (device globals: no allocation allowed)
__device__ float  g_agg[(size_t)NN * D];
__device__ float  g_x1[(size_t)NN * D];
__device__ __half g_xh[(size_t)NN * D];    // fp16 copy of input x (layer-1 gather)
__device__ __half g_x1h[(size_t)NN * D];   // fp16 copy of x1 (layer-2 gather)
__device__ __half g_ph[(size_t)NN * DO];   // fp16 p (layer-3 gather payload)
__device__ float  g_q[(size_t)NN * DO];
__device__ int    g_deg[NN];
__device__ int    g_off[NN];
__device__ int    g_off2[NN];
__device__ int    g_bsum[SCAN_B];
__device__ int    g_esrc[NE];

__device__ __forceinline__ float gelu_exact(float v) {
    return 0.5f * v * (1.0f + erff(v * 0.70710678118654752f));
}

__device__ __forceinline__ uint32_t f2tf32(float f) {
    uint32_t r;
    asm("cvt.rna.tf32.f32 %0, %1;" : "=r"(r) : "f"(f));
    return r;
}

__device__ __forceinline__ void mma_tf32(float* d,
    uint32_t a0, uint32_t a1, uint32_t a2, uint32_t a3,
    uint32_t b0, uint32_t b1)
{
    asm volatile(
        "mma.sync.aligned.m16n8k8.row.col.f32.tf32.tf32.f32 "
        "{%0,%1,%2,%3}, {%4,%5,%6,%7}, {%8,%9}, {%0,%1,%2,%3};"
        : "+f"(d[0]), "+f"(d[1]), "+f"(d[2]), "+f"(d[3])
        : "r"(a0), "r"(a1), "r"(a2), "r"(a3), "r"(b0), "r"(b1));
}

// ---------------- CSR build ----------------

__global__ void count_deg(const int* __restrict__ dst) {
    int e = blockIdx.x * blockDim.x + threadIdx.x;
    if (e < NE) atomicAdd(&g_deg[dst[e]], 1);
}

__global__ void scan_local() {
    __shared__ int s[SCAN_T];
    int t = threadIdx.x;
    int i = blockIdx.x * SCAN_T + t;
    int v = (i < NN) ? g_deg[i] : 0;
    s[t] = v;
    __syncthreads();
    #pragma unroll
    for (int off = 1; off < SCAN_T; off <<= 1) {
        int a = (t >= off) ? s[t - off] : 0;
        __syncthreads();
        s[t] += a;
        __syncthreads();
    }
    if (i < NN) g_off[i] = s[t] - v;
    if (t == SCAN_T - 1) g_bsum[blockIdx.x] = s[t];
}

__global__ void scan_add2() {   // <<<(NN+255)/256, 128>>>, 2 elems/thread
    __shared__ int s[128];
    int t = threadIdx.x;
    int v = (t < SCAN_B) ? g_bsum[t] : 0;
    s[t] = v;
    __syncthreads();
    #pragma unroll
    for (int off = 1; off < 128; off <<= 1) {
        int a = (t >= off) ? s[t - off] : 0;
        __syncthreads();
        s[t] += a;
        __syncthreads();
    }
    int inc = s[t];
    __syncthreads();
    s[t] = inc - v;                               // exclusive
    __syncthreads();
    int i0 = blockIdx.x * 256 + t;
    int i1 = i0 + 128;
    if (i0 < NN) { int o = g_off[i0] + s[i0 / SCAN_T]; g_off[i0] = o; g_off2[i0] = o; }
    if (i1 < NN) { int o = g_off[i1] + s[i1 / SCAN_T]; g_off[i1] = o; g_off2[i1] = o; }
}

__global__ void fill_edges(const int* __restrict__ src, const int* __restrict__ dst) {
    int e = blockIdx.x * blockDim.x + threadIdx.x;
    if (e >= NE) return;
    int d = dst[e];
    int pos = atomicAdd(&g_off2[d], 1);
    g_esrc[pos] = src[e];
}

// ---------------- fp32 -> fp16 conversion (input x) ----------------

__global__ void cvt_half(const float* __restrict__ x) {
    int i = blockIdx.x * blockDim.x + threadIdx.x;
    if (i < NN * D / 2) {
        float2 v = ((const float2*)x)[i];
        ((half2*)g_xh)[i] = __float22half2_rn(v);
    }
}

// ------- gather mean-aggregation over fp16 rows, 8-way MLP -------
// One warp per node; lane holds dims [4*lane..4*lane+3] (one uint2 = 4 halves).

__global__ __launch_bounds__(256) void gather128h(const __half* __restrict__ xh) {
    int gw = (blockIdx.x * blockDim.x + threadIdx.x) >> 5;
    int lane = threadIdx.x & 31;
    if (gw >= NN) return;
    int start = g_off[gw], deg = g_deg[gw];
    const int* es = g_esrc + start;
    const uint2* x8 = (const uint2*)xh;   // 32 uint2 per node row
    float4 a0 = make_float4(0.f,0.f,0.f,0.f), a1 = a0, a2 = a0, a3 = a0;
    int e = 0;
    for (; e + 8 <= deg; e += 8) {
        int i0 = __ldg(es + e),     i1 = __ldg(es + e + 1);
        int i2 = __ldg(es + e + 2), i3 = __ldg(es + e + 3);
        int i4 = __ldg(es + e + 4), i5 = __ldg(es + e + 5);
        int i6 = __ldg(es + e + 6), i7 = __ldg(es + e + 7);
        uint2 u0 = __ldg(&x8[(size_t)i0 * 32 + lane]);
        uint2 u1 = __ldg(&x8[(size_t)i1 * 32 + lane]);
        uint2 u2 = __ldg(&x8[(size_t)i2 * 32 + lane]);
        uint2 u3 = __ldg(&x8[(size_t)i3 * 32 + lane]);
        uint2 u4 = __ldg(&x8[(size_t)i4 * 32 + lane]);
        uint2 u5 = __ldg(&x8[(size_t)i5 * 32 + lane]);
        uint2 u6 = __ldg(&x8[(size_t)i6 * 32 + lane]);
        uint2 u7 = __ldg(&x8[(size_t)i7 * 32 + lane]);
        float2 f;
        f = __half22float2(*(half2*)&u0.x); a0.x += f.x; a0.y += f.y;
        f = __half22float2(*(half2*)&u0.y); a0.z += f.x; a0.w += f.y;
        f = __half22float2(*(half2*)&u1.x); a1.x += f.x; a1.y += f.y;
        f = __half22float2(*(half2*)&u1.y); a1.z += f.x; a1.w += f.y;
        f = __half22float2(*(half2*)&u2.x); a2.x += f.x; a2.y += f.y;
        f = __half22float2(*(half2*)&u2.y); a2.z += f.x; a2.w += f.y;
        f = __half22float2(*(half2*)&u3.x); a3.x += f.x; a3.y += f.y;
        f = __half22float2(*(half2*)&u3.y); a3.z += f.x; a3.w += f.y;
        f = __half22float2(*(half2*)&u4.x); a0.x += f.x; a0.y += f.y;
        f = __half22float2(*(half2*)&u4.y); a0.z += f.x; a0.w += f.y;
        f = __half22float2(*(half2*)&u5.x); a1.x += f.x; a1.y += f.y;
        f = __half22float2(*(half2*)&u5.y); a1.z += f.x; a1.w += f.y;
        f = __half22float2(*(half2*)&u6.x); a2.x += f.x; a2.y += f.y;
        f = __half22float2(*(half2*)&u6.y); a2.z += f.x; a2.w += f.y;
        f = __half22float2(*(half2*)&u7.x); a3.x += f.x; a3.y += f.y;
        f = __half22float2(*(half2*)&u7.y); a3.z += f.x; a3.w += f.y;
    }
    for (; e + 4 <= deg; e += 4) {
        int i0 = __ldg(es + e),     i1 = __ldg(es + e + 1);
        int i2 = __ldg(es + e + 2), i3 = __ldg(es + e + 3);
        uint2 u0 = __ldg(&x8[(size_t)i0 * 32 + lane]);
        uint2 u1 = __ldg(&x8[(size_t)i1 * 32 + lane]);
        uint2 u2 = __ldg(&x8[(size_t)i2 * 32 + lane]);
        uint2 u3 = __ldg(&x8[(size_t)i3 * 32 + lane]);
        float2 f;
        f = __half22float2(*(half2*)&u0.x); a0.x += f.x; a0.y += f.y;
        f = __half22float2(*(half2*)&u0.y); a0.z += f.x; a0.w += f.y;
        f = __half22float2(*(half2*)&u1.x); a1.x += f.x; a1.y += f.y;
        f = __half22float2(*(half2*)&u1.y); a1.z += f.x; a1.w += f.y;
        f = __half22float2(*(half2*)&u2.x); a2.x += f.x; a2.y += f.y;
        f = __half22float2(*(half2*)&u2.y); a2.z += f.x; a2.w += f.y;
        f = __half22float2(*(half2*)&u3.x); a3.x += f.x; a3.y += f.y;
        f = __half22float2(*(half2*)&u3.y); a3.z += f.x; a3.w += f.y;
    }
    for (; e < deg; e++) {
        int i0 = __ldg(es + e);
        uint2 u0 = __ldg(&x8[(size_t)i0 * 32 + lane]);
        float2 f;
        f = __half22float2(*(half2*)&u0.x); a0.x += f.x; a0.y += f.y;
        f = __half22float2(*(half2*)&u0.y); a0.z += f.x; a0.w += f.y;
    }
    float inv = 1.0f / fmaxf((float)deg, 1.0f);
    float4 r;
    r.x = (a0.x + a1.x + a2.x + a3.x) * inv;
    r.y = (a0.y + a1.y + a2.y + a3.y) * inv;
    r.z = (a0.z + a1.z + a2.z + a3.z) * inv;
    r.w = (a0.w + a1.w + a2.w + a3.w) * inv;
    ((float4*)g_agg)[(size_t)gw * 32 + lane] = r;
}

// ---- SAGE block (layer 1): tf32 mma, double-buffered operand staging ----
// Also emits x1 as fp16 (g_x1h) for the layer-2 gather.

__global__ __launch_bounds__(256, 2) void sage_tc2(
    const float* __restrict__ xin,
    const float* __restrict__ Wl, const float* __restrict__ bl,
    const float* __restrict__ Wr,
    const float* __restrict__ gma, const float* __restrict__ bta,
    float* __restrict__ xout)
{
    extern __shared__ uint32_t dsm[];
    uint32_t* buf0 = dsm;
    uint32_t* buf1 = dsm + BUFU;
    float*    sred = (float*)(dsm + 2 * BUFU);

    const int tid = threadIdx.x;
    const int node0 = blockIdx.x * 64;
    const int warp = tid >> 5, lane = tid & 31;
    const int wm = warp & 1, wn = warp >> 1;
    const int g = lane >> 2, t4 = lane & 3;

    const int an0 = tid >> 3, an1 = (tid + 256) >> 3, af = tid & 7;
    const int koff = (af >> 1) * 8 + (af & 1);
    const float4 f4z = make_float4(0.f, 0.f, 0.f, 0.f);

    auto ldA = [&](int kc, float4& r0, float4& r1) {
        const float4* Asrc = (kc < 4) ? (const float4*)g_agg : (const float4*)xin;
        int kb = (kc & 3) * 8;
        int gn0 = node0 + an0, gn1 = node0 + an1;
        r0 = (gn0 < NN) ? __ldg(&Asrc[(size_t)gn0 * 32 + kb + af]) : f4z;
        r1 = (gn1 < NN) ? __ldg(&Asrc[(size_t)gn1 * 32 + kb + af]) : f4z;
    };
    auto stA = [&](uint32_t* B, float4 r0, float4 r1) {
        B[an0 * 40 + koff + 0] = f2tf32(r0.x);
        B[an0 * 40 + koff + 2] = f2tf32(r0.y);
        B[an0 * 40 + koff + 4] = f2tf32(r0.z);
        B[an0 * 40 + koff + 6] = f2tf32(r0.w);
        B[an1 * 40 + koff + 0] = f2tf32(r1.x);
        B[an1 * 40 + koff + 2] = f2tf32(r1.y);
        B[an1 * 40 + koff + 4] = f2tf32(r1.z);
        B[an1 * 40 + koff + 6] = f2tf32(r1.w);
    };
    auto ldW = [&](int kc, float4* w) {
        const float4* Wsrc = (kc < 4) ? (const float4*)Wl : (const float4*)Wr;
        int kr0 = (kc & 3) * 32;
        int p0 = 2 * warp, p1 = 2 * warp + 1;
        int k0 = (p0 >> 2) * 8 + (p0 & 3);
        int k1 = (p1 >> 2) * 8 + (p1 & 3);
        w[0] = __ldg(&Wsrc[(size_t)(kr0 + k0) * 32 + lane]);
        w[1] = __ldg(&Wsrc[(size_t)(kr0 + k0 + 4) * 32 + lane]);
        w[2] = __ldg(&Wsrc[(size_t)(kr0 + k1) * 32 + lane]);
        w[3] = __ldg(&Wsrc[(size_t)(kr0 + k1 + 4) * 32 + lane]);
    };
    auto stW = [&](uint32_t* B, const float4* w) {
        uint4* W4 = (uint4*)(B + 2560);
        #pragma unroll
        for (int q = 0; q < 2; q++) {
            int p = 2 * warp + q;
            float4 lo = w[2 * q], hi = w[2 * q + 1];
            W4[p * 66 + 2 * lane]     = make_uint4(f2tf32(lo.x), f2tf32(hi.x),
                                                   f2tf32(lo.y), f2tf32(hi.y));
            W4[p * 66 + 2 * lane + 1] = make_uint4(f2tf32(lo.z), f2tf32(hi.z),
                                                   f2tf32(lo.w), f2tf32(hi.w));
        }
    };

    float acc0[4][4], acc1[4][4];
    #pragma unroll
    for (int i = 0; i < 4; i++)
        #pragma unroll
        for (int j = 0; j < 4; j++) { acc0[i][j] = 0.f; acc1[i][j] = 0.f; }

    {
        float4 a0, a1, w0[4];
        ldA(0, a0, a1); ldW(0, w0);
        stA(buf0, a0, a1); stW(buf0, w0);
    }
    __syncthreads();

    const int C = wm * 32;
    for (int kc = 0; kc < 8; kc++) {
        float4 na0, na1, nw[4];
        if (kc < 7) { ldA(kc + 1, na0, na1); ldW(kc + 1, nw); }
        uint32_t* B = (kc & 1) ? buf1 : buf0;
        const uint2* Apk = (const uint2*)B;
        const uint2* Wpk = (const uint2*)(B + 2560);
        #pragma unroll
        for (int kk = 0; kk < 4; kk++) {
            int pbase = kk * 4 + t4;
            uint2 qa0 = Apk[(C + g)      * ASTR2 + pbase];
            uint2 qa1 = Apk[(C + g + 8)  * ASTR2 + pbase];
            uint2 qa2 = Apk[(C + g + 16) * ASTR2 + pbase];
            uint2 qa3 = Apk[(C + g + 24) * ASTR2 + pbase];
            #pragma unroll
            for (int nt = 0; nt < 4; nt++) {
                uint2 qb = Wpk[pbase * WSTR2 + wn * 32 + nt * 8 + g];
                mma_tf32(acc0[nt], qa0.x, qa1.x, qa0.y, qa1.y, qb.x, qb.y);
                mma_tf32(acc1[nt], qa2.x, qa3.x, qa2.y, qa3.y, qb.x, qb.y);
            }
        }
        if (kc < 7) {
            uint32_t* Bn = (kc & 1) ? buf0 : buf1;
            stA(Bn, na0, na1); stW(Bn, nw);
            __syncthreads();
        }
    }

    // ---- epilogue: + bl -> LN (128 cols) -> GELU -> + residual ----
    float s[4][2];
    #pragma unroll
    for (int r = 0; r < 4; r++) { s[r][0] = 0.f; s[r][1] = 0.f; }
    #pragma unroll
    for (int nt = 0; nt < 4; nt++) {
        int c = wn * 32 + nt * 8 + 2 * t4;
        float2 blv = *(const float2*)&bl[c];
        acc0[nt][0] += blv.x; acc0[nt][1] += blv.y;
        acc0[nt][2] += blv.x; acc0[nt][3] += blv.y;
        acc1[nt][0] += blv.x; acc1[nt][1] += blv.y;
        acc1[nt][2] += blv.x; acc1[nt][3] += blv.y;
        s[0][0] += acc0[nt][0] + acc0[nt][1];
        s[0][1] += acc0[nt][0]*acc0[nt][0] + acc0[nt][1]*acc0[nt][1];
        s[1][0] += acc0[nt][2] + acc0[nt][3];
        s[1][1] += acc0[nt][2]*acc0[nt][2] + acc0[nt][3]*acc0[nt][3];
        s[2][0] += acc1[nt][0] + acc1[nt][1];
        s[2][1] += acc1[nt][0]*acc1[nt][0] + acc1[nt][1]*acc1[nt][1];
        s[3][0] += acc1[nt][2] + acc1[nt][3];
        s[3][1] += acc1[nt][2]*acc1[nt][2] + acc1[nt][3]*acc1[nt][3];
    }
    #pragma unroll
    for (int off = 1; off <= 2; off <<= 1)
        #pragma unroll
        for (int r = 0; r < 4; r++) {
            s[r][0] += __shfl_xor_sync(0xffffffffu, s[r][0], off);
            s[r][1] += __shfl_xor_sync(0xffffffffu, s[r][1], off);
        }
    if (t4 == 0) {
        #pragma unroll
        for (int r = 0; r < 4; r++) {
            sred[(wn * 64 + C + g + r * 8) * 2 + 0] = s[r][0];
            sred[(wn * 64 + C + g + r * 8) * 2 + 1] = s[r][1];
        }
    }
    __syncthreads();

    float mu[4], rs[4];
    #pragma unroll
    for (int r = 0; r < 4; r++) {
        int row = C + g + r * 8;
        float S1 = sred[(0 * 64 + row) * 2] + sred[(1 * 64 + row) * 2]
                 + sred[(2 * 64 + row) * 2] + sred[(3 * 64 + row) * 2];
        float S2 = sred[(0 * 64 + row) * 2 + 1] + sred[(1 * 64 + row) * 2 + 1]
                 + sred[(2 * 64 + row) * 2 + 1] + sred[(3 * 64 + row) * 2 + 1];
        mu[r] = S1 * (1.0f / 128.0f);
        float var = S2 * (1.0f / 128.0f) - mu[r] * mu[r];
        rs[r] = rsqrtf(var + 1e-5f);
    }

    #pragma unroll
    for (int nt = 0; nt < 4; nt++) {
        int c = wn * 32 + nt * 8 + 2 * t4;
        float2 gv = *(const float2*)&gma[c];
        float2 bv = *(const float2*)&bta[c];
        #pragma unroll
        for (int r = 0; r < 4; r++) {
            int gn = node0 + C + g + r * 8;
            if (gn >= NN) continue;
            float v0, v1;
            if (r == 0)      { v0 = acc0[nt][0]; v1 = acc0[nt][1]; }
            else if (r == 1) { v0 = acc0[nt][2]; v1 = acc0[nt][3]; }
            else if (r == 2) { v0 = acc1[nt][0]; v1 = acc1[nt][1]; }
            else             { v0 = acc1[nt][2]; v1 = acc1[nt][3]; }
            float2 res = *(const float2*)&xin[(size_t)gn * D + c];
            float o0 = gelu_exact((v0 - mu[r]) * rs[r] * gv.x + bv.x) + res.x;
            float o1 = gelu_exact((v1 - mu[r]) * rs[r] * gv.y + bv.y) + res.y;
            *(float2*)&xout[(size_t)gn * D + c] = make_float2(o0, o1);
            ((half2*)g_x1h)[(size_t)gn * 64 + (c >> 1)] =
                __float22half2_rn(make_float2(o0, o1));
        }
    }
}

// ---- sage_pq (layer 2 + pq GEMM fused): p emitted as fp16 for the L3 gather ----

__global__ __launch_bounds__(256, 2) void sage_pq(
    const float* __restrict__ xin,
    const float* __restrict__ Wl, const float* __restrict__ bl,
    const float* __restrict__ Wr,
    const float* __restrict__ gma, const float* __restrict__ bta,
    const float* __restrict__ Wl3, const float* __restrict__ Wr3)
{
    extern __shared__ uint32_t dsm[];
    uint32_t* buf0 = dsm;                          // 6784 u32
    float*    sred = (float*)(dsm + BUFU);         //  512 u32
    uint32_t* Xr   = dsm + BUFU + 512;             // 8448 u32 (buf1 = first 6784)
    uint32_t* buf1 = Xr;

    const int tid = threadIdx.x;
    const int node0 = blockIdx.x * 64;
    const int warp = tid >> 5, lane = tid & 31;
    const int wm = warp & 1, wn = warp >> 1;
    const int g = lane >> 2, t4 = lane & 3;

    const int an0 = tid >> 3, an1 = (tid + 256) >> 3, af = tid & 7;
    const int koff = (af >> 1) * 8 + (af & 1);
    const float4 f4z = make_float4(0.f, 0.f, 0.f, 0.f);

    auto ldA = [&](int kc, float4& r0, float4& r1) {
        const float4* Asrc = (kc < 4) ? (const float4*)g_agg : (const float4*)xin;
        int kb = (kc & 3) * 8;
        int gn0 = node0 + an0, gn1 = node0 + an1;
        r0 = (gn0 < NN) ? __ldg(&Asrc[(size_t)gn0 * 32 + kb + af]) : f4z;
        r1 = (gn1 < NN) ? __ldg(&Asrc[(size_t)gn1 * 32 + kb + af]) : f4z;
    };
    auto stA = [&](uint32_t* B, float4 r0, float4 r1) {
        B[an0 * 40 + koff + 0] = f2tf32(r0.x);
        B[an0 * 40 + koff + 2] = f2tf32(r0.y);
        B[an0 * 40 + koff + 4] = f2tf32(r0.z);
        B[an0 * 40 + koff + 6] = f2tf32(r0.w);
        B[an1 * 40 + koff + 0] = f2tf32(r1.x);
        B[an1 * 40 + koff + 2] = f2tf32(r1.y);
        B[an1 * 40 + koff + 4] = f2tf32(r1.z);
        B[an1 * 40 + koff + 6] = f2tf32(r1.w);
    };
    auto ldW = [&](int kc, float4* w) {
        const float4* Wsrc = (kc < 4) ? (const float4*)Wl : (const float4*)Wr;
        int kr0 = (kc & 3) * 32;
        int p0 = 2 * warp, p1 = 2 * warp + 1;
        int k0 = (p0 >> 2) * 8 + (p0 & 3);
        int k1 = (p1 >> 2) * 8 + (p1 & 3);
        w[0] = __ldg(&Wsrc[(size_t)(kr0 + k0) * 32 + lane]);
        w[1] = __ldg(&Wsrc[(size_t)(kr0 + k0 + 4) * 32 + lane]);
        w[2] = __ldg(&Wsrc[(size_t)(kr0 + k1) * 32 + lane]);
        w[3] = __ldg(&Wsrc[(size_t)(kr0 + k1 + 4) * 32 + lane]);
    };
    auto ldW3 = [&](int kc, float4* w) {
        int kr0 = kc * 32;
        int p0 = 2 * warp, p1 = 2 * warp + 1;
        int k0 = (p0 >> 2) * 8 + (p0 & 3);
        int k1 = (p1 >> 2) * 8 + (p1 & 3);
        const float4* Wsrc = (lane < 16) ? (const float4*)Wl3 : (const float4*)Wr3;
        int cl = lane & 15;
        w[0] = __ldg(&Wsrc[(size_t)(kr0 + k0) * 16 + cl]);
        w[1] = __ldg(&Wsrc[(size_t)(kr0 + k0 + 4) * 16 + cl]);
        w[2] = __ldg(&Wsrc[(size_t)(kr0 + k1) * 16 + cl]);
        w[3] = __ldg(&Wsrc[(size_t)(kr0 + k1 + 4) * 16 + cl]);
    };
    auto stW = [&](uint32_t* B, const float4* w) {
        uint4* W4 = (uint4*)(B + 2560);
        #pragma unroll
        for (int q = 0; q < 2; q++) {
            int p = 2 * warp + q;
            float4 lo = w[2 * q], hi = w[2 * q + 1];
            W4[p * 66 + 2 * lane]     = make_uint4(f2tf32(lo.x), f2tf32(hi.x),
                                                   f2tf32(lo.y), f2tf32(hi.y));
            W4[p * 66 + 2 * lane + 1] = make_uint4(f2tf32(lo.z), f2tf32(hi.z),
                                                   f2tf32(lo.w), f2tf32(hi.w));
        }
    };

    float acc0[4][4], acc1[4][4];
    #pragma unroll
    for (int i = 0; i < 4; i++)
        #pragma unroll
        for (int j = 0; j < 4; j++) { acc0[i][j] = 0.f; acc1[i][j] = 0.f; }

    {
        float4 a0, a1, w0[4];
        ldA(0, a0, a1); ldW(0, w0);
        stA(buf0, a0, a1); stW(buf0, w0);
    }
    __syncthreads();

    const int C = wm * 32;
    for (int kc = 0; kc < 8; kc++) {
        float4 na0, na1, nw[4];
        if (kc < 7) { ldA(kc + 1, na0, na1); ldW(kc + 1, nw); }
        uint32_t* B = (kc & 1) ? buf1 : buf0;
        const uint2* Apk = (const uint2*)B;
        const uint2* Wpk = (const uint2*)(B + 2560);
        #pragma unroll
        for (int kk = 0; kk < 4; kk++) {
            int pbase = kk * 4 + t4;
            uint2 qa0 = Apk[(C + g)      * ASTR2 + pbase];
            uint2 qa1 = Apk[(C + g + 8)  * ASTR2 + pbase];
            uint2 qa2 = Apk[(C + g + 16) * ASTR2 + pbase];
            uint2 qa3 = Apk[(C + g + 24) * ASTR2 + pbase];
            #pragma unroll
            for (int nt = 0; nt < 4; nt++) {
                uint2 qb = Wpk[pbase * WSTR2 + wn * 32 + nt * 8 + g];
                mma_tf32(acc0[nt], qa0.x, qa1.x, qa0.y, qa1.y, qb.x, qb.y);
                mma_tf32(acc1[nt], qa2.x, qa3.x, qa2.y, qa3.y, qb.x, qb.y);
            }
        }
        if (kc < 7) {
            uint32_t* Bn = (kc & 1) ? buf0 : buf1;
            stA(Bn, na0, na1); stW(Bn, nw);
            __syncthreads();
        }
    }
    __syncthreads();   // all warps done reading buf1 (Xr region) before epilogue writes Xr

    // ---- epilogue: + bl -> LN -> GELU -> + residual -> Xr (tf32, smem only) ----
    float s[4][2];
    #pragma unroll
    for (int r = 0; r < 4; r++) { s[r][0] = 0.f; s[r][1] = 0.f; }
    #pragma unroll
    for (int nt = 0; nt < 4; nt++) {
        int c = wn * 32 + nt * 8 + 2 * t4;
        float2 blv = *(const float2*)&bl[c];
        acc0[nt][0] += blv.x; acc0[nt][1] += blv.y;
        acc0[nt][2] += blv.x; acc0[nt][3] += blv.y;
        acc1[nt][0] += blv.x; acc1[nt][1] += blv.y;
        acc1[nt][2] += blv.x; acc1[nt][3] += blv.y;
        s[0][0] += acc0[nt][0] + acc0[nt][1];
        s[0][1] += acc0[nt][0]*acc0[nt][0] + acc0[nt][1]*acc0[nt][1];
        s[1][0] += acc0[nt][2] + acc0[nt][3];
        s[1][1] += acc0[nt][2]*acc0[nt][2] + acc0[nt][3]*acc0[nt][3];
        s[2][0] += acc1[nt][0] + acc1[nt][1];
        s[2][1] += acc1[nt][0]*acc1[nt][0] + acc1[nt][1]*acc1[nt][1];
        s[3][0] += acc1[nt][2] + acc1[nt][3];
        s[3][1] += acc1[nt][2]*acc1[nt][2] + acc1[nt][3]*acc1[nt][3];
    }
    #pragma unroll
    for (int off = 1; off <= 2; off <<= 1)
        #pragma unroll
        for (int r = 0; r < 4; r++) {
            s[r][0] += __shfl_xor_sync(0xffffffffu, s[r][0], off);
            s[r][1] += __shfl_xor_sync(0xffffffffu, s[r][1], off);
        }
    if (t4 == 0) {
        #pragma unroll
        for (int r = 0; r < 4; r++) {
            sred[(wn * 64 + C + g + r * 8) * 2 + 0] = s[r][0];
            sred[(wn * 64 + C + g + r * 8) * 2 + 1] = s[r][1];
        }
    }
    __syncthreads();

    float mu[4], rs[4];
    #pragma unroll
    for (int r = 0; r < 4; r++) {
        int row = C + g + r * 8;
        float S1 = sred[(0 * 64 + row) * 2] + sred[(1 * 64 + row) * 2]
                 + sred[(2 * 64 + row) * 2] + sred[(3 * 64 + row) * 2];
        float S2 = sred[(0 * 64 + row) * 2 + 1] + sred[(1 * 64 + row) * 2 + 1]
                 + sred[(2 * 64 + row) * 2 + 1] + sred[(3 * 64 + row) * 2 + 1];
        mu[r] = S1 * (1.0f / 128.0f);
        float var = S2 * (1.0f / 128.0f) - mu[r] * mu[r];
        rs[r] = rsqrtf(var + 1e-5f);
    }

    #pragma unroll
    for (int nt = 0; nt < 4; nt++) {
        int c = wn * 32 + nt * 8 + 2 * t4;
        float2 gv = *(const float2*)&gma[c];
        float2 bv = *(const float2*)&bta[c];
        #pragma unroll
        for (int r = 0; r < 4; r++) {
            int row = C + g + r * 8;
            int gn = node0 + row;
            float v0, v1;
            if (r == 0)      { v0 = acc0[nt][0]; v1 = acc0[nt][1]; }
            else if (r == 1) { v0 = acc0[nt][2]; v1 = acc0[nt][3]; }
            else if (r == 2) { v0 = acc1[nt][0]; v1 = acc1[nt][1]; }
            else             { v0 = acc1[nt][2]; v1 = acc1[nt][3]; }
            float o0 = 0.f, o1 = 0.f;
            if (gn < NN) {
                float2 res = *(const float2*)&xin[(size_t)gn * D + c];
                o0 = gelu_exact((v0 - mu[r]) * rs[r] * gv.x + bv.x) + res.x;
                o1 = gelu_exact((v1 - mu[r]) * rs[r] * gv.y + bv.y) + res.y;
            }
            Xr[row * ARSTR + c]     = f2tf32(o0);
            Xr[row * ARSTR + c + 1] = f2tf32(o1);
        }
    }
    __syncthreads();   // Xr complete; buf0's W region free for reuse

    // ---- pq GEMM: [p|q] = x2 @ [Wl3|Wr3], K=128 from resident Xr ----
    #pragma unroll
    for (int i = 0; i < 4; i++)
        #pragma unroll
        for (int j = 0; j < 4; j++) { acc0[i][j] = 0.f; acc1[i][j] = 0.f; }

    {
        float4 w0[4];
        ldW3(0, w0);
        stW(buf0, w0);
    }
    __syncthreads();

    const uint2* WpkQ = (const uint2*)(buf0 + 2560);
    for (int kc = 0; kc < 4; kc++) {
        float4 nw[4];
        if (kc < 3) ldW3(kc + 1, nw);
        #pragma unroll
        for (int kk = 0; kk < 4; kk++) {
            int kb = kc * 32 + kk * 8 + t4;
            uint32_t a00 = Xr[(C + g)      * ARSTR + kb];
            uint32_t a10 = Xr[(C + g + 8)  * ARSTR + kb];
            uint32_t a20 = Xr[(C + g + 16) * ARSTR + kb];
            uint32_t a30 = Xr[(C + g + 24) * ARSTR + kb];
            uint32_t a01 = Xr[(C + g)      * ARSTR + kb + 4];
            uint32_t a11 = Xr[(C + g + 8)  * ARSTR + kb + 4];
            uint32_t a21 = Xr[(C + g + 16) * ARSTR + kb + 4];
            uint32_t a31 = Xr[(C + g + 24) * ARSTR + kb + 4];
            #pragma unroll
            for (int nt = 0; nt < 4; nt++) {
                uint2 qb = WpkQ[(kk * 4 + t4) * WSTR2 + wn * 32 + nt * 8 + g];
                mma_tf32(acc0[nt], a00, a10, a01, a11, qb.x, qb.y);
                mma_tf32(acc1[nt], a20, a30, a21, a31, qb.x, qb.y);
            }
        }
        __syncthreads();
        if (kc < 3) { stW(buf0, nw); __syncthreads(); }
    }

    #pragma unroll
    for (int nt = 0; nt < 4; nt++) {
        int c = wn * 32 + nt * 8 + 2 * t4;
        #pragma unroll
        for (int r = 0; r < 4; r++) {
            int gn = node0 + C + g + r * 8;
            if (gn >= NN) continue;
            float v0, v1;
            if (r == 0)      { v0 = acc0[nt][0]; v1 = acc0[nt][1]; }
            else if (r == 1) { v0 = acc0[nt][2]; v1 = acc0[nt][3]; }
            else if (r == 2) { v0 = acc1[nt][0]; v1 = acc1[nt][1]; }
            else             { v0 = acc1[nt][2]; v1 = acc1[nt][3]; }
            if (c < 64) {
                ((half2*)g_ph)[(size_t)gn * 32 + (c >> 1)] =
                    __float22half2_rn(make_float2(v0, v1));
            } else {
                int cc = c & 63;
                *(float2*)&g_q[(size_t)gn * DO + cc] = make_float2(v0, v1);
            }
        }
    }
}

// ---- out_fused64: gather(p, fp16) + gelu(+q+bl3) -> LN(64) -> @Wc + bcls ----
// 64-node tile per block; 8-way MLP gather; lane holds dims 2*lane, 2*lane+1.

__global__ __launch_bounds__(256) void out_fused64(
    const float* __restrict__ bl3,
    const float* __restrict__ gc, const float* __restrict__ bc,
    const float* __restrict__ Wc, const float* __restrict__ bcls,
    float* __restrict__ out)
{
    __shared__ float Wcs[DO * NC];
    __shared__ float bcs[NC];
    __shared__ float Vs[64 * 66];
    const int tid = threadIdx.x;
    const int node0 = blockIdx.x * 64;
    const int warp = tid >> 5, lane = tid & 31;

    for (int i = tid; i < DO * NC; i += 256)
        Wcs[i] = __ldg(&Wc[i]);
    if (tid < NC) bcs[tid] = __ldg(&bcls[tid]);

    float2 b3v = __ldg(&((const float2*)bl3)[lane]);
    float2 gcv = __ldg(&((const float2*)gc)[lane]);
    float2 bcv = __ldg(&((const float2*)bc)[lane]);
    const uint32_t* p4 = (const uint32_t*)g_ph;   // 32 uints per node row

    for (int nn = 0; nn < 8; nn++) {
        int ln = warp * 8 + nn;
        int gn = node0 + ln;
        if (gn >= NN) break;
        int start = g_off[gn], deg = g_deg[gn];
        const int* es = g_esrc + start;
        float2 a0 = make_float2(0.f, 0.f), a1 = a0, a2 = a0, a3 = a0;
        int e = 0;
        for (; e + 8 <= deg; e += 8) {
            int i0 = __ldg(es + e),     i1 = __ldg(es + e + 1);
            int i2 = __ldg(es + e + 2), i3 = __ldg(es + e + 3);
            int i4 = __ldg(es + e + 4), i5 = __ldg(es + e + 5);
            int i6 = __ldg(es + e + 6), i7 = __ldg(es + e + 7);
            uint32_t u0 = __ldg(&p4[(size_t)i0 * 32 + lane]);
            uint32_t u1 = __ldg(&p4[(size_t)i1 * 32 + lane]);
            uint32_t u2 = __ldg(&p4[(size_t)i2 * 32 + lane]);
            uint32_t u3 = __ldg(&p4[(size_t)i3 * 32 + lane]);
            uint32_t u4 = __ldg(&p4[(size_t)i4 * 32 + lane]);
            uint32_t u5 = __ldg(&p4[(size_t)i5 * 32 + lane]);
            uint32_t u6 = __ldg(&p4[(size_t)i6 * 32 + lane]);
            uint32_t u7 = __ldg(&p4[(size_t)i7 * 32 + lane]);
            float2 f;
            f = __half22float2(*(half2*)&u0); a0.x += f.x; a0.y += f.y;
            f = __half22float2(*(half2*)&u1); a1.x += f.x; a1.y += f.y;
            f = __half22float2(*(half2*)&u2); a2.x += f.x; a2.y += f.y;
            f = __half22float2(*(half2*)&u3); a3.x += f.x; a3.y += f.y;
            f = __half22float2(*(half2*)&u4); a0.x += f.x; a0.y += f.y;
            f = __half22float2(*(half2*)&u5); a1.x += f.x; a1.y += f.y;
            f = __half22float2(*(half2*)&u6); a2.x += f.x; a2.y += f.y;
            f = __half22float2(*(half2*)&u7); a3.x += f.x; a3.y += f.y;
        }
        for (; e < deg; e++) {
            int i0 = __ldg(es + e);
            uint32_t u0 = __ldg(&p4[(size_t)i0 * 32 + lane]);
            float2 f = __half22float2(*(half2*)&u0);
            a0.x += f.x; a0.y += f.y;
        }
        float inv = 1.0f / fmaxf((float)deg, 1.0f);
        float agx = (a0.x + a1.x + a2.x + a3.x) * inv;
        float agy = (a0.y + a1.y + a2.y + a3.y) * inv;

        float2 q = __ldg(&((const float2*)g_q)[(size_t)gn * 32 + lane]);
        float u0 = gelu_exact(agx + q.x + b3v.x);
        float u1 = gelu_exact(agy + q.y + b3v.y);
        float s1 = u0 + u1, s2 = u0 * u0 + u1 * u1;
        #pragma unroll
        for (int off = 16; off; off >>= 1) {
            s1 += __shfl_xor_sync(0xffffffffu, s1, off);
            s2 += __shfl_xor_sync(0xffffffffu, s2, off);
        }
        float mu = s1 * (1.0f / 64.0f);
        float var = s2 * (1.0f / 64.0f) - mu * mu;
        float rstd = rsqrtf(var + 1e-5f);
        Vs[ln * 66 + 2 * lane]     = (u0 - mu) * rstd * gcv.x + bcv.x;
        Vs[ln * 66 + 2 * lane + 1] = (u1 - mu) * rstd * gcv.y + bcv.y;
    }
    __syncthreads();

    int n = tid >> 2, cg = (tid & 3) * 10;
    int gn = node0 + n;
    if (gn >= NN) return;
    float o[10];
    #pragma unroll
    for (int j = 0; j < 10; j++) o[j] = bcs[cg + j];
    #pragma unroll 8
    for (int k = 0; k < DO; k++) {
        float vv = Vs[n * 66 + k];
        #pragma unroll
        for (int j = 0; j < 10; j++)
            o[j] += vv * Wcs[k * NC + cg + j];
    }
    #pragma unroll
    for (int j = 0; j < 10; j++)
        out[(size_t)gn * NC + cg + j] = o[j];
}

// ---------------- launcher ----------------

extern "C" void kernel_launch(void* const* d_in, const int* in_sizes, int n_in,
                              void* d_out, int out_size)
{
    const float* x    = (const float*)d_in[0];
    const int*   ei   = (const int*)d_in[1];
    const float* Wl1  = (const float*)d_in[2];
    const float* bl1  = (const float*)d_in[3];
    const float* Wr1  = (const float*)d_in[4];
    const float* g1   = (const float*)d_in[5];
    const float* b1   = (const float*)d_in[6];
    const float* Wl2  = (const float*)d_in[7];
    const float* bl2  = (const float*)d_in[8];
    const float* Wr2  = (const float*)d_in[9];
    const float* g2   = (const float*)d_in[10];
    const float* b2   = (const float*)d_in[11];
    const float* Wl3  = (const float*)d_in[12];
    const float* bl3  = (const float*)d_in[13];
    const float* Wr3  = (const float*)d_in[14];
    const float* gc   = (const float*)d_in[15];
    const float* bc   = (const float*)d_in[16];
    const float* Wc   = (const float*)d_in[17];
    const float* bcls = (const float*)d_in[18];
    const int* src = ei;
    const int* dst = ei + NE;
    float* out = (float*)d_out;

    void *p_x1 = nullptr, *p_deg = nullptr, *p_xh = nullptr, *p_x1h = nullptr;
    cudaGetSymbolAddress(&p_x1, g_x1);
    cudaGetSymbolAddress(&p_deg, g_deg);
    cudaGetSymbolAddress(&p_xh, g_xh);
    cudaGetSymbolAddress(&p_x1h, g_x1h);

    const int smem_tc2 = (2 * BUFU + 512) * 4;            // 56320 B
    const int smem_pq  = (BUFU + 512 + 8448) * 4;         // 62976 B
    cudaFuncSetAttribute(sage_tc2, cudaFuncAttributeMaxDynamicSharedMemorySize, smem_tc2);
    cudaFuncSetAttribute(sage_pq, cudaFuncAttributeMaxDynamicSharedMemorySize, smem_pq);

    const int nbn = (NN + 63) / 64;
    const int nbe = (NE + 255) / 256;
    const int nbw = ((NN * 32) + 255) / 256;   // one warp per node

    // CSR build + fp16 conversion of x
    cudaMemsetAsync(p_deg, 0, (size_t)NN * sizeof(int));
    cvt_half<<<(NN * D / 2 + 255) / 256, 256>>>(x);
    count_deg<<<nbe, 256>>>(dst);
    scan_local<<<SCAN_B, SCAN_T>>>();
    scan_add2<<<(NN + 255) / 256, 128>>>();
    fill_edges<<<nbe, 256>>>(src, dst);

    // Layer 1 (fp16 gather payload)
    gather128h<<<nbw, 256>>>((const __half*)p_xh);
    sage_tc2<<<nbn, 256, smem_tc2>>>(x, Wl1, bl1, Wr1, g1, b1, (float*)p_x1);

    // Layer 2 + pq GEMM fused (fp16 gather payload; x2 never hits global)
    gather128h<<<nbw, 256>>>((const __half*)p_x1h);
    sage_pq<<<nbn, 256, smem_pq>>>((const float*)p_x1, Wl2, bl2, Wr2, g2, b2, Wl3, Wr3);

    // Layer 3 tail: fused gather(p, fp16) + epilogue + classifier
    out_fused64<<<nbn, 256>>>(bl3, gc, bc, Wc, bcls, out);
}